// round 1
// baseline (speedup 1.0000x reference)
#include <cuda_runtime.h>

#define D_MODEL 2048
#define KV_DIM  512
#define BATCH   2
#define SEQ     2048
#define MTOK    4096   // BATCH * SEQ
#define HEADS   32
#define HDIM    64

// Scratch (device globals: no allocations allowed)
__device__ float g_Q[(size_t)MTOK * D_MODEL];   // 32 MB
__device__ float g_K[(size_t)MTOK * KV_DIM];    //  8 MB
__device__ float g_V[(size_t)MTOK * KV_DIM];    //  8 MB
__device__ float g_C[(size_t)MTOK * D_MODEL];   // 32 MB (attention context)

// ---------------------------------------------------------------------------
// fp32 SGEMM: C[M,N] = A[M,K] @ B[K,N] + bias[N]
// 128x128 block tile, K-tile 8, 256 threads, 8x8 per-thread micro-tile.
// Requires M%128==0, N%128==0, K%8==0 (true for all shapes here).
// ---------------------------------------------------------------------------
__global__ __launch_bounds__(256)
void sgemm_bias(const float* __restrict__ A, const float* __restrict__ B,
                const float* __restrict__ bias, float* __restrict__ C,
                int M, int N, int K)
{
    __shared__ float As[8][128];   // [k][m]
    __shared__ float Bs[8][128];   // [k][n]

    const int tid = threadIdx.x;
    const int bx = blockIdx.x, by = blockIdx.y;
    const int tm = tid >> 4;        // 0..15
    const int tn = tid & 15;        // 0..15

    const int arow = tid >> 1;          // 0..127
    const int acol = (tid & 1) << 2;    // 0 or 4
    const int brow = tid >> 5;          // 0..7
    const int bcol = (tid & 31) << 2;   // 0..124

    const float* Ap = A + (size_t)(by * 128 + arow) * K + acol;
    const float* Bp = B + (size_t)brow * N + bx * 128 + bcol;

    float acc[8][8];
    #pragma unroll
    for (int i = 0; i < 8; i++)
        #pragma unroll
        for (int j = 0; j < 8; j++) acc[i][j] = 0.f;

    for (int k0 = 0; k0 < K; k0 += 8) {
        float4 a = *(const float4*)Ap;
        float4 b = *(const float4*)Bp;
        As[acol + 0][arow] = a.x;
        As[acol + 1][arow] = a.y;
        As[acol + 2][arow] = a.z;
        As[acol + 3][arow] = a.w;
        *(float4*)&Bs[brow][bcol] = b;
        __syncthreads();

        #pragma unroll
        for (int kk = 0; kk < 8; kk++) {
            float av[8], bv[8];
            *(float4*)&av[0] = *(const float4*)&As[kk][tm * 8];
            *(float4*)&av[4] = *(const float4*)&As[kk][tm * 8 + 4];
            *(float4*)&bv[0] = *(const float4*)&Bs[kk][tn * 8];
            *(float4*)&bv[4] = *(const float4*)&Bs[kk][tn * 8 + 4];
            #pragma unroll
            for (int i = 0; i < 8; i++)
                #pragma unroll
                for (int j = 0; j < 8; j++)
                    acc[i][j] = fmaf(av[i], bv[j], acc[i][j]);
        }
        __syncthreads();
        Ap += 8;
        Bp += (size_t)8 * N;
    }

    #pragma unroll
    for (int i = 0; i < 8; i++) {
        const int row = by * 128 + tm * 8 + i;
        #pragma unroll
        for (int j = 0; j < 8; j += 4) {
            const int col = bx * 128 + tn * 8 + j;
            float4 o;
            o.x = acc[i][j + 0] + bias[col + 0];
            o.y = acc[i][j + 1] + bias[col + 1];
            o.z = acc[i][j + 2] + bias[col + 2];
            o.w = acc[i][j + 3] + bias[col + 3];
            *(float4*)(C + (size_t)row * N + col) = o;
        }
    }
}

// ---------------------------------------------------------------------------
// Flash attention (non-causal, GQA group 4), fp32.
// One CTA = (batch b, head h, 64-query tile). Loops over 32 K/V tiles of 64.
// Q is pre-scaled by 1/sqrt(Dh) at smem load time.
// Layouts in smem: Qs[d][r], Ks[d][j] (transposed for vector LDS),
//                  Vs[j][d], Ps[r][j].
// ---------------------------------------------------------------------------
#define QS_STR 65
#define KS_STR 68
#define VS_STR 68
#define PS_STR 68
#define ATTN_SMEM_FLOATS (64 * QS_STR + 64 * KS_STR + 64 * VS_STR + 64 * PS_STR)
#define ATTN_SMEM_BYTES  (ATTN_SMEM_FLOATS * 4)

__global__ __launch_bounds__(256)
void attn_kernel(const float* __restrict__ Q, const float* __restrict__ K,
                 const float* __restrict__ V, float* __restrict__ C)
{
    extern __shared__ float sm[];
    float* Qs = sm;                       // 64 x QS_STR  [d][r]
    float* Ks = Qs + 64 * QS_STR;         // 64 x KS_STR  [d][j]
    float* Vs = Ks + 64 * KS_STR;         // 64 x VS_STR  [j][d]
    float* Ps = Vs + 64 * VS_STR;         // 64 x PS_STR  [r][j]

    const int tid = threadIdx.x;
    const int qt = blockIdx.x;
    const int h  = blockIdx.y;
    const int b  = blockIdx.z;
    const int hkv = h >> 2;               // GQA group of 4

    const int ty = tid >> 4, tx = tid & 15;
    const int r0 = ty << 2, c0 = tx << 2;

    // Load Q tile (scaled), transposed into Qs[d][r]
    #pragma unroll
    for (int it = 0; it < 4; it++) {
        int fi = it * 256 + tid;
        int r = fi >> 4;
        int c = (fi & 15) << 2;
        float4 q = *(const float4*)(Q + (size_t)(b * SEQ + qt * 64 + r) * D_MODEL
                                      + h * HDIM + c);
        Qs[(c + 0) * QS_STR + r] = q.x * 0.125f;
        Qs[(c + 1) * QS_STR + r] = q.y * 0.125f;
        Qs[(c + 2) * QS_STR + r] = q.z * 0.125f;
        Qs[(c + 3) * QS_STR + r] = q.w * 0.125f;
    }

    float m[4], l[4], o[4][4];
    #pragma unroll
    for (int i = 0; i < 4; i++) {
        m[i] = -1e30f; l[i] = 0.f;
        #pragma unroll
        for (int j = 0; j < 4; j++) o[i][j] = 0.f;
    }

    for (int kt = 0; kt < SEQ / 64; kt++) {
        __syncthreads();   // previous PV done (and Q load on first iter)

        // Load K (transposed) + V tiles
        #pragma unroll
        for (int it = 0; it < 4; it++) {
            int fi = it * 256 + tid;
            int r = fi >> 4;
            int c = (fi & 15) << 2;
            const size_t grow = (size_t)(b * SEQ + kt * 64 + r) * KV_DIM + hkv * HDIM + c;
            float4 kv = *(const float4*)(K + grow);
            Ks[(c + 0) * KS_STR + r] = kv.x;
            Ks[(c + 1) * KS_STR + r] = kv.y;
            Ks[(c + 2) * KS_STR + r] = kv.z;
            Ks[(c + 3) * KS_STR + r] = kv.w;
            float4 vv = *(const float4*)(V + grow);
            *(float4*)&Vs[r * VS_STR + c] = vv;
        }
        __syncthreads();

        // S tile: s[i][j] = (scaled Q row r0+i) . (K row c0+j)
        float s[4][4];
        #pragma unroll
        for (int i = 0; i < 4; i++)
            #pragma unroll
            for (int j = 0; j < 4; j++) s[i][j] = 0.f;

        #pragma unroll 16
        for (int d = 0; d < 64; d++) {
            float q0 = Qs[d * QS_STR + r0 + 0];
            float q1 = Qs[d * QS_STR + r0 + 1];
            float q2 = Qs[d * QS_STR + r0 + 2];
            float q3 = Qs[d * QS_STR + r0 + 3];
            float4 kk = *(const float4*)&Ks[d * KS_STR + c0];
            s[0][0] = fmaf(q0, kk.x, s[0][0]); s[0][1] = fmaf(q0, kk.y, s[0][1]);
            s[0][2] = fmaf(q0, kk.z, s[0][2]); s[0][3] = fmaf(q0, kk.w, s[0][3]);
            s[1][0] = fmaf(q1, kk.x, s[1][0]); s[1][1] = fmaf(q1, kk.y, s[1][1]);
            s[1][2] = fmaf(q1, kk.z, s[1][2]); s[1][3] = fmaf(q1, kk.w, s[1][3]);
            s[2][0] = fmaf(q2, kk.x, s[2][0]); s[2][1] = fmaf(q2, kk.y, s[2][1]);
            s[2][2] = fmaf(q2, kk.z, s[2][2]); s[2][3] = fmaf(q2, kk.w, s[2][3]);
            s[3][0] = fmaf(q3, kk.x, s[3][0]); s[3][1] = fmaf(q3, kk.y, s[3][1]);
            s[3][2] = fmaf(q3, kk.z, s[3][2]); s[3][3] = fmaf(q3, kk.w, s[3][3]);
        }

        // Online softmax (rows r0..r0+3; reduce across the 16 tx lanes)
        #pragma unroll
        for (int i = 0; i < 4; i++) {
            float mx = fmaxf(fmaxf(s[i][0], s[i][1]), fmaxf(s[i][2], s[i][3]));
            mx = fmaxf(mx, __shfl_xor_sync(0xffffffffu, mx, 1));
            mx = fmaxf(mx, __shfl_xor_sync(0xffffffffu, mx, 2));
            mx = fmaxf(mx, __shfl_xor_sync(0xffffffffu, mx, 4));
            mx = fmaxf(mx, __shfl_xor_sync(0xffffffffu, mx, 8));
            float mnew = fmaxf(m[i], mx);
            float corr = __expf(m[i] - mnew);
            m[i] = mnew;
            float p0 = __expf(s[i][0] - mnew);
            float p1 = __expf(s[i][1] - mnew);
            float p2 = __expf(s[i][2] - mnew);
            float p3 = __expf(s[i][3] - mnew);
            float rs = (p0 + p1) + (p2 + p3);
            rs += __shfl_xor_sync(0xffffffffu, rs, 1);
            rs += __shfl_xor_sync(0xffffffffu, rs, 2);
            rs += __shfl_xor_sync(0xffffffffu, rs, 4);
            rs += __shfl_xor_sync(0xffffffffu, rs, 8);
            l[i] = l[i] * corr + rs;
            o[i][0] *= corr; o[i][1] *= corr; o[i][2] *= corr; o[i][3] *= corr;
            float4 pv = make_float4(p0, p1, p2, p3);
            *(float4*)&Ps[(r0 + i) * PS_STR + c0] = pv;
        }
        __syncthreads();

        // O += P @ V
        #pragma unroll
        for (int j2 = 0; j2 < 64; j2 += 4) {
            float pr[4][4];
            #pragma unroll
            for (int i = 0; i < 4; i++)
                *(float4*)pr[i] = *(const float4*)&Ps[(r0 + i) * PS_STR + j2];
            #pragma unroll
            for (int jj = 0; jj < 4; jj++) {
                float4 v = *(const float4*)&Vs[(j2 + jj) * VS_STR + c0];
                #pragma unroll
                for (int i = 0; i < 4; i++) {
                    o[i][0] = fmaf(pr[i][jj], v.x, o[i][0]);
                    o[i][1] = fmaf(pr[i][jj], v.y, o[i][1]);
                    o[i][2] = fmaf(pr[i][jj], v.z, o[i][2]);
                    o[i][3] = fmaf(pr[i][jj], v.w, o[i][3]);
                }
            }
        }
    }

    // Normalize and write context
    #pragma unroll
    for (int i = 0; i < 4; i++) {
        float inv = 1.0f / l[i];
        float4 out4 = make_float4(o[i][0] * inv, o[i][1] * inv,
                                  o[i][2] * inv, o[i][3] * inv);
        *(float4*)(C + (size_t)(b * SEQ + qt * 64 + r0 + i) * D_MODEL
                     + h * HDIM + c0) = out4;
    }
}

// ---------------------------------------------------------------------------
// Launch
// ---------------------------------------------------------------------------
extern "C" void kernel_launch(void* const* d_in, const int* in_sizes, int n_in,
                              void* d_out, int out_size)
{
    const float* x  = (const float*)d_in[0];
    const float* Wq = (const float*)d_in[1];
    const float* bq = (const float*)d_in[2];
    const float* Wk = (const float*)d_in[3];
    const float* bk = (const float*)d_in[4];
    const float* Wv = (const float*)d_in[5];
    const float* bv = (const float*)d_in[6];
    const float* Wo = (const float*)d_in[7];
    const float* bo = (const float*)d_in[8];
    float* out = (float*)d_out;

    float *pQ, *pK, *pV, *pC;
    cudaGetSymbolAddress((void**)&pQ, g_Q);
    cudaGetSymbolAddress((void**)&pK, g_K);
    cudaGetSymbolAddress((void**)&pV, g_V);
    cudaGetSymbolAddress((void**)&pC, g_C);

    // Projections
    sgemm_bias<<<dim3(D_MODEL / 128, MTOK / 128), 256>>>(x, Wq, bq, pQ, MTOK, D_MODEL, D_MODEL);
    sgemm_bias<<<dim3(KV_DIM  / 128, MTOK / 128), 256>>>(x, Wk, bk, pK, MTOK, KV_DIM,  D_MODEL);
    sgemm_bias<<<dim3(KV_DIM  / 128, MTOK / 128), 256>>>(x, Wv, bv, pV, MTOK, KV_DIM,  D_MODEL);

    // Attention
    cudaFuncSetAttribute(attn_kernel, cudaFuncAttributeMaxDynamicSharedMemorySize,
                         ATTN_SMEM_BYTES);
    attn_kernel<<<dim3(SEQ / 64, HEADS, BATCH), 256, ATTN_SMEM_BYTES>>>(pQ, pK, pV, pC);

    // Output projection
    sgemm_bias<<<dim3(D_MODEL / 128, MTOK / 128), 256>>>(pC, Wo, bo, out, MTOK, D_MODEL, D_MODEL);
}

// round 2
// speedup vs baseline: 3.3240x; 3.3240x over previous
#include <cuda_runtime.h>

#define D_MODEL 2048
#define KV_DIM  512
#define BATCH   2
#define SEQ     2048
#define MTOK    4096   // BATCH * SEQ
#define HEADS   32
#define HDIM    64

// Scratch (device globals: no allocations allowed)
__device__ float g_Q[(size_t)MTOK * D_MODEL];   // 32 MB
__device__ float g_K[(size_t)MTOK * KV_DIM];    //  8 MB
__device__ float g_V[(size_t)MTOK * KV_DIM];    //  8 MB
__device__ float g_C[(size_t)MTOK * D_MODEL];   // 32 MB (attention context)

// ---------------------------------------------------------------------------
// tf32 helpers
// ---------------------------------------------------------------------------
__device__ __forceinline__ unsigned f2tf(float x) {
    unsigned u;
    asm("cvt.rna.tf32.f32 %0, %1;" : "=r"(u) : "f"(x));
    return u;
}
__device__ __forceinline__ float f2tff(float x) { return __uint_as_float(f2tf(x)); }

// D += A(16x8, tf32, row) * B(8x8, tf32, col)
__device__ __forceinline__ void mma8(float* d, const unsigned* a, const unsigned* b) {
    asm volatile(
        "mma.sync.aligned.m16n8k8.row.col.f32.tf32.tf32.f32 "
        "{%0,%1,%2,%3},{%4,%5,%6,%7},{%8,%9},{%0,%1,%2,%3};"
        : "+f"(d[0]), "+f"(d[1]), "+f"(d[2]), "+f"(d[3])
        : "r"(a[0]), "r"(a[1]), "r"(a[2]), "r"(a[3]), "r"(b[0]), "r"(b[1]));
}

// ---------------------------------------------------------------------------
// tf32 tensor-core GEMM: C[M,N] = A[M,K] @ B[K,N] + bias[N]
// CTA tile 128x128, K-tile 32, 8 warps (2x4), warp tile 64x32.
// As[m][k] stride 36  -> fragment LDS bank = lane (conflict-free)
// Bs[k][n] stride 136 -> fragment LDS conflict-free
// ---------------------------------------------------------------------------
#define AS_STR 36
#define BS_STR 136

__global__ __launch_bounds__(256)
void gemm_tf32(const float* __restrict__ A, const float* __restrict__ B,
               const float* __restrict__ bias, float* __restrict__ C,
               int M, int N, int K)
{
    __shared__ float As[128 * AS_STR];
    __shared__ float Bs[32 * BS_STR];

    const int tid  = threadIdx.x;
    const int lane = tid & 31;
    const int wid  = tid >> 5;
    const int wm   = (wid >> 2) * 64;   // warp m offset (0/64)
    const int wn   = (wid & 3) * 32;    // warp n offset
    const int bx = blockIdx.x, by = blockIdx.y;
    const int g  = lane >> 2;           // groupID (row within fragment)
    const int tg = lane & 3;            // thread-in-group (k / col pairs)

    const int ar = tid >> 3;            // 0..31 (A row within pass)
    const int ac = (tid & 7) << 2;      // 0..28 (A col, float4)
    const int br = tid >> 5;            // 0..7  (B row within pass)
    const int bc = lane << 2;           // 0..124 (B col, float4)

    float acc[4][4][4];
    #pragma unroll
    for (int mt = 0; mt < 4; mt++)
        #pragma unroll
        for (int nt = 0; nt < 4; nt++)
            #pragma unroll
            for (int i = 0; i < 4; i++) acc[mt][nt][i] = 0.f;

    for (int k0 = 0; k0 < K; k0 += 32) {
        // Load A tile [128][32] -> As[m][k]
        #pragma unroll
        for (int p = 0; p < 4; p++) {
            float4 a4 = *(const float4*)(A + (size_t)(by * 128 + p * 32 + ar) * K + k0 + ac);
            float4 t4 = make_float4(f2tff(a4.x), f2tff(a4.y), f2tff(a4.z), f2tff(a4.w));
            *(float4*)&As[(p * 32 + ar) * AS_STR + ac] = t4;
        }
        // Load B tile [32][128] -> Bs[k][n]
        #pragma unroll
        for (int p = 0; p < 4; p++) {
            float4 b4 = *(const float4*)(B + (size_t)(k0 + p * 8 + br) * N + bx * 128 + bc);
            float4 t4 = make_float4(f2tff(b4.x), f2tff(b4.y), f2tff(b4.z), f2tff(b4.w));
            *(float4*)&Bs[(p * 8 + br) * BS_STR + bc] = t4;
        }
        __syncthreads();

        #pragma unroll
        for (int kk = 0; kk < 32; kk += 8) {
            unsigned af[4][4], bf[4][2];
            #pragma unroll
            for (int mt = 0; mt < 4; mt++) {
                const float* s = &As[(wm + mt * 16 + g) * AS_STR + kk + tg];
                af[mt][0] = __float_as_uint(s[0]);
                af[mt][1] = __float_as_uint(s[8 * AS_STR]);
                af[mt][2] = __float_as_uint(s[4]);
                af[mt][3] = __float_as_uint(s[8 * AS_STR + 4]);
            }
            #pragma unroll
            for (int nt = 0; nt < 4; nt++) {
                const float* s = &Bs[(kk + tg) * BS_STR + wn + nt * 8 + g];
                bf[nt][0] = __float_as_uint(s[0]);
                bf[nt][1] = __float_as_uint(s[4 * BS_STR]);
            }
            #pragma unroll
            for (int mt = 0; mt < 4; mt++)
                #pragma unroll
                for (int nt = 0; nt < 4; nt++)
                    mma8(acc[mt][nt], af[mt], bf[nt]);
        }
        __syncthreads();
    }

    // Epilogue: c0,c1 -> (row, 2*tg), (row, 2*tg+1); c2,c3 -> row+8
    #pragma unroll
    for (int mt = 0; mt < 4; mt++) {
        const int row = by * 128 + wm + mt * 16 + g;
        #pragma unroll
        for (int nt = 0; nt < 4; nt++) {
            const int col = bx * 128 + wn + nt * 8 + tg * 2;
            const float b0 = bias[col], b1 = bias[col + 1];
            float2 lo = make_float2(acc[mt][nt][0] + b0, acc[mt][nt][1] + b1);
            float2 hi = make_float2(acc[mt][nt][2] + b0, acc[mt][nt][3] + b1);
            *(float2*)(C + (size_t)row * N + col) = lo;
            *(float2*)(C + (size_t)(row + 8) * N + col) = hi;
        }
    }
}

// ---------------------------------------------------------------------------
// Flash attention with tf32 tensor cores (non-causal, GQA group 4).
// One CTA = (b, h, 64-query tile), 4 warps; warp owns 16 query rows.
// Q fragments held in registers across all K-tiles.
// smem: Ks[j][d] stride 68, Vs[j][d] stride 72, QP[r][*] stride 68
// (Q staging, reused as P buffer). All fragment LDS conflict-free.
// ---------------------------------------------------------------------------
#define KS_STR 68
#define VS_STR 72
#define PS_STR 68
#define ATTN_SMEM_FLOATS (64 * KS_STR + 64 * VS_STR + 64 * PS_STR)
#define ATTN_SMEM_BYTES  (ATTN_SMEM_FLOATS * 4)

__global__ __launch_bounds__(128)
void attn_tf32(const float* __restrict__ Q, const float* __restrict__ K,
               const float* __restrict__ V, float* __restrict__ C)
{
    extern __shared__ float sm[];
    float* Ks = sm;                          // [64][KS_STR]
    float* Vs = Ks + 64 * KS_STR;            // [64][VS_STR]
    float* QP = Vs + 64 * VS_STR;            // [64][PS_STR]

    const int tid  = threadIdx.x;
    const int lane = tid & 31;
    const int wid  = tid >> 5;               // 0..3
    const int g    = lane >> 2;              // 0..7
    const int tg   = lane & 3;               // 0..3
    const int r0   = wid * 16;               // warp's query-row base

    const int qt = blockIdx.x;
    const int h  = blockIdx.y;
    const int b  = blockIdx.z;
    const int hkv = h >> 2;

    // Stage Q (scaled, tf32) into QP[r][d]
    #pragma unroll
    for (int p = 0; p < 8; p++) {
        int idx = p * 128 + tid;
        int r = idx >> 4;
        int c4 = (idx & 15) << 2;
        float4 q4 = *(const float4*)(Q + (size_t)(b * SEQ + qt * 64 + r) * D_MODEL
                                       + h * HDIM + c4);
        float4 t4 = make_float4(f2tff(q4.x * 0.125f), f2tff(q4.y * 0.125f),
                                f2tff(q4.z * 0.125f), f2tff(q4.w * 0.125f));
        *(float4*)&QP[r * PS_STR + c4] = t4;
    }
    __syncthreads();

    // Q fragments in registers: 8 k-groups x 4 regs
    unsigned aQ[8][4];
    #pragma unroll
    for (int gk = 0; gk < 8; gk++) {
        const float* s = &QP[(r0 + g) * PS_STR + gk * 8 + tg];
        aQ[gk][0] = __float_as_uint(s[0]);
        aQ[gk][1] = __float_as_uint(s[8 * PS_STR]);
        aQ[gk][2] = __float_as_uint(s[4]);
        aQ[gk][3] = __float_as_uint(s[8 * PS_STR + 4]);
    }

    float o[8][4];
    #pragma unroll
    for (int nt = 0; nt < 8; nt++)
        #pragma unroll
        for (int i = 0; i < 4; i++) o[nt][i] = 0.f;
    float m0 = -1e30f, m1 = -1e30f, l0 = 0.f, l1 = 0.f;

    for (int kt = 0; kt < SEQ / 64; kt++) {
        __syncthreads();   // protect Ks/Vs reuse (and QP frag loads on iter 0)

        // Load K,V tiles [64 keys][64 dims]
        #pragma unroll
        for (int p = 0; p < 8; p++) {
            int idx = p * 128 + tid;
            int j = idx >> 4;
            int c4 = (idx & 15) << 2;
            size_t gofs = (size_t)(b * SEQ + kt * 64 + j) * KV_DIM + hkv * HDIM + c4;
            float4 k4 = *(const float4*)(K + gofs);
            *(float4*)&Ks[j * KS_STR + c4] =
                make_float4(f2tff(k4.x), f2tff(k4.y), f2tff(k4.z), f2tff(k4.w));
            float4 v4 = *(const float4*)(V + gofs);
            *(float4*)&Vs[j * VS_STR + c4] =
                make_float4(f2tff(v4.x), f2tff(v4.y), f2tff(v4.z), f2tff(v4.w));
        }
        __syncthreads();

        // S = Q @ K^T  (warp: 16 rows x 64 keys)
        float s[8][4];
        #pragma unroll
        for (int nt = 0; nt < 8; nt++)
            #pragma unroll
            for (int i = 0; i < 4; i++) s[nt][i] = 0.f;

        #pragma unroll
        for (int gk = 0; gk < 8; gk++) {
            #pragma unroll
            for (int nt = 0; nt < 8; nt++) {
                unsigned bk[2];
                const float* kb = &Ks[(nt * 8 + g) * KS_STR + gk * 8 + tg];
                bk[0] = __float_as_uint(kb[0]);
                bk[1] = __float_as_uint(kb[4]);
                mma8(s[nt], aQ[gk], bk);
            }
        }

        // Online softmax. Thread covers rows (r0+g) via c0/c1 and (r0+g+8) via c2/c3.
        float tm0 = -1e30f, tm1 = -1e30f;
        #pragma unroll
        for (int nt = 0; nt < 8; nt++) {
            tm0 = fmaxf(tm0, fmaxf(s[nt][0], s[nt][1]));
            tm1 = fmaxf(tm1, fmaxf(s[nt][2], s[nt][3]));
        }
        tm0 = fmaxf(tm0, __shfl_xor_sync(0xffffffffu, tm0, 1));
        tm0 = fmaxf(tm0, __shfl_xor_sync(0xffffffffu, tm0, 2));
        tm1 = fmaxf(tm1, __shfl_xor_sync(0xffffffffu, tm1, 1));
        tm1 = fmaxf(tm1, __shfl_xor_sync(0xffffffffu, tm1, 2));

        float nm0 = fmaxf(m0, tm0), nm1 = fmaxf(m1, tm1);
        float c0 = __expf(m0 - nm0), c1 = __expf(m1 - nm1);
        m0 = nm0; m1 = nm1;

        float rs0 = 0.f, rs1 = 0.f;
        #pragma unroll
        for (int nt = 0; nt < 8; nt++) {
            float p0 = __expf(s[nt][0] - m0);
            float p1 = __expf(s[nt][1] - m0);
            float p2 = __expf(s[nt][2] - m1);
            float p3 = __expf(s[nt][3] - m1);
            rs0 += p0 + p1;
            rs1 += p2 + p3;
            *(float2*)&QP[(r0 + g) * PS_STR + nt * 8 + tg * 2] =
                make_float2(f2tff(p0), f2tff(p1));
            *(float2*)&QP[(r0 + g + 8) * PS_STR + nt * 8 + tg * 2] =
                make_float2(f2tff(p2), f2tff(p3));
            o[nt][0] *= c0; o[nt][1] *= c0;
            o[nt][2] *= c1; o[nt][3] *= c1;
        }
        rs0 += __shfl_xor_sync(0xffffffffu, rs0, 1);
        rs0 += __shfl_xor_sync(0xffffffffu, rs0, 2);
        rs1 += __shfl_xor_sync(0xffffffffu, rs1, 1);
        rs1 += __shfl_xor_sync(0xffffffffu, rs1, 2);
        l0 = l0 * c0 + rs0;
        l1 = l1 * c1 + rs1;
        __syncwarp();

        // O += P @ V  (warp-private P rows)
        #pragma unroll
        for (int gk = 0; gk < 8; gk++) {
            unsigned aP[4];
            const float* pb = &QP[(r0 + g) * PS_STR + gk * 8 + tg];
            aP[0] = __float_as_uint(pb[0]);
            aP[1] = __float_as_uint(pb[8 * PS_STR]);
            aP[2] = __float_as_uint(pb[4]);
            aP[3] = __float_as_uint(pb[8 * PS_STR + 4]);
            #pragma unroll
            for (int nt = 0; nt < 8; nt++) {
                unsigned bv[2];
                const float* vb = &Vs[(gk * 8 + tg) * VS_STR + nt * 8 + g];
                bv[0] = __float_as_uint(vb[0]);
                bv[1] = __float_as_uint(vb[4 * VS_STR]);
                mma8(o[nt], aP, bv);
            }
        }
    }

    // Normalize and write context
    const float i0 = 1.f / l0, i1 = 1.f / l1;
    #pragma unroll
    for (int nt = 0; nt < 8; nt++) {
        const size_t row = (size_t)(b * SEQ + qt * 64 + r0 + g);
        const int col = h * HDIM + nt * 8 + tg * 2;
        *(float2*)(C + row * D_MODEL + col) =
            make_float2(o[nt][0] * i0, o[nt][1] * i0);
        *(float2*)(C + (row + 8) * D_MODEL + col) =
            make_float2(o[nt][2] * i1, o[nt][3] * i1);
    }
}

// ---------------------------------------------------------------------------
// Launch
// ---------------------------------------------------------------------------
extern "C" void kernel_launch(void* const* d_in, const int* in_sizes, int n_in,
                              void* d_out, int out_size)
{
    const float* x  = (const float*)d_in[0];
    const float* Wq = (const float*)d_in[1];
    const float* bq = (const float*)d_in[2];
    const float* Wk = (const float*)d_in[3];
    const float* bk = (const float*)d_in[4];
    const float* Wv = (const float*)d_in[5];
    const float* bv = (const float*)d_in[6];
    const float* Wo = (const float*)d_in[7];
    const float* bo = (const float*)d_in[8];
    float* out = (float*)d_out;

    float *pQ, *pK, *pV, *pC;
    cudaGetSymbolAddress((void**)&pQ, g_Q);
    cudaGetSymbolAddress((void**)&pK, g_K);
    cudaGetSymbolAddress((void**)&pV, g_V);
    cudaGetSymbolAddress((void**)&pC, g_C);

    // Projections (tf32 tensor cores)
    gemm_tf32<<<dim3(D_MODEL / 128, MTOK / 128), 256>>>(x, Wq, bq, pQ, MTOK, D_MODEL, D_MODEL);
    gemm_tf32<<<dim3(KV_DIM  / 128, MTOK / 128), 256>>>(x, Wk, bk, pK, MTOK, KV_DIM,  D_MODEL);
    gemm_tf32<<<dim3(KV_DIM  / 128, MTOK / 128), 256>>>(x, Wv, bv, pV, MTOK, KV_DIM,  D_MODEL);

    // Attention (tf32 tensor cores)
    cudaFuncSetAttribute(attn_tf32, cudaFuncAttributeMaxDynamicSharedMemorySize,
                         ATTN_SMEM_BYTES);
    attn_tf32<<<dim3(SEQ / 64, HEADS, BATCH), 128, ATTN_SMEM_BYTES>>>(pQ, pK, pV, pC);

    // Output projection
    gemm_tf32<<<dim3(D_MODEL / 128, MTOK / 128), 256>>>(pC, Wo, bo, out, MTOK, D_MODEL, D_MODEL);
}

// round 3
// speedup vs baseline: 3.8469x; 1.1573x over previous
#include <cuda_runtime.h>
#include <cstdint>

#define D_MODEL 2048
#define KV_DIM  512
#define BATCH   2
#define SEQ     2048
#define MTOK    4096
#define HEADS   32
#define HDIM    64

// Scratch (device globals: no allocations allowed)
__device__ float g_Q[(size_t)MTOK * D_MODEL];
__device__ float g_K[(size_t)MTOK * KV_DIM];
__device__ float g_V[(size_t)MTOK * KV_DIM];
__device__ float g_C[(size_t)MTOK * D_MODEL];

// ---------------------------------------------------------------------------
// helpers
// ---------------------------------------------------------------------------
__device__ __forceinline__ unsigned f2tf(float x) {
    unsigned u;
    asm("cvt.rna.tf32.f32 %0, %1;" : "=r"(u) : "f"(x));
    return u;
}
__device__ __forceinline__ float f2tff(float x) { return __uint_as_float(f2tf(x)); }

__device__ __forceinline__ void mma8(float* d, const unsigned* a, const unsigned* b) {
    asm volatile(
        "mma.sync.aligned.m16n8k8.row.col.f32.tf32.tf32.f32 "
        "{%0,%1,%2,%3},{%4,%5,%6,%7},{%8,%9},{%0,%1,%2,%3};"
        : "+f"(d[0]), "+f"(d[1]), "+f"(d[2]), "+f"(d[3])
        : "r"(a[0]), "r"(a[1]), "r"(a[2]), "r"(a[3]), "r"(b[0]), "r"(b[1]));
}

__device__ __forceinline__ void cpa16(uint32_t dst, const void* src) {
    asm volatile("cp.async.cg.shared.global [%0], [%1], 16;" :: "r"(dst), "l"(src));
}
__device__ __forceinline__ void cpa_commit() {
    asm volatile("cp.async.commit_group;");
}
template <int N>
__device__ __forceinline__ void cpa_wait() {
    asm volatile("cp.async.wait_group %0;" :: "n"(N));
}

// ---------------------------------------------------------------------------
// tf32 GEMM core: C[M,N] = A[M,K] @ B[K,N] + bias, CTA tile 128x128, K-step 32,
// cp.async double-buffered raw fp32 tiles, cvt.rna at fragment load.
// As[m][k] stride 36 (144B, 16B-aligned rows), Bs[k][n] stride 136 (544B).
// Fragment LDS conflict-free: A bank=4g+tg, B bank=8tg+g.
// ---------------------------------------------------------------------------
#define AS_STR 36
#define BS_STR 136
#define A_STAGE (128 * AS_STR)
#define B_STAGE (32 * BS_STR)
#define GEMM_SMEM_BYTES ((2 * A_STAGE + 2 * B_STAGE) * 4)

__device__ __forceinline__ void gemm_core(
    const float* __restrict__ A, const float* __restrict__ B,
    const float* __restrict__ bias, float* __restrict__ C,
    int N, int K, int colb, int by)
{
    extern __shared__ float sm[];
    float* As = sm;
    float* Bs = sm + 2 * A_STAGE;
    const uint32_t as_u = (uint32_t)__cvta_generic_to_shared(As);
    const uint32_t bs_u = (uint32_t)__cvta_generic_to_shared(Bs);

    const int tid  = threadIdx.x;
    const int lane = tid & 31;
    const int wid  = tid >> 5;
    const int wm = (wid >> 2) * 64;
    const int wn = (wid & 3) * 32;
    const int g  = lane >> 2;
    const int tg = lane & 3;

    float acc[4][4][4];
    #pragma unroll
    for (int mt = 0; mt < 4; mt++)
        #pragma unroll
        for (int nt = 0; nt < 4; nt++)
            #pragma unroll
            for (int i = 0; i < 4; i++) acc[mt][nt][i] = 0.f;

    auto issue = [&](int st, int k0) {
        #pragma unroll
        for (int p = 0; p < 4; p++) {          // A tile 128x32
            int idx = p * 256 + tid;
            int r = idx >> 3, c = (idx & 7) << 2;
            cpa16(as_u + (uint32_t)(st * A_STAGE + r * AS_STR + c) * 4,
                  A + (size_t)(by * 128 + r) * K + k0 + c);
        }
        #pragma unroll
        for (int p = 0; p < 4; p++) {          // B tile 32x128
            int idx = p * 256 + tid;
            int r = idx >> 5, c = (idx & 31) << 2;
            cpa16(bs_u + (uint32_t)(st * B_STAGE + r * BS_STR + c) * 4,
                  B + (size_t)(k0 + r) * N + colb + c);
        }
    };

    const int nsteps = K / 32;
    issue(0, 0);
    cpa_commit();

    for (int s = 0; s < nsteps; s++) {
        if (s + 1 < nsteps) {
            issue((s + 1) & 1, (s + 1) * 32);
            cpa_commit();
            cpa_wait<1>();
        } else {
            cpa_wait<0>();
        }
        __syncthreads();

        const float* Ab = As + (s & 1) * A_STAGE;
        const float* Bb = Bs + (s & 1) * B_STAGE;

        #pragma unroll
        for (int kk = 0; kk < 32; kk += 8) {
            unsigned af[4][4], bf[4][2];
            #pragma unroll
            for (int mt = 0; mt < 4; mt++) {
                const float* sp = &Ab[(wm + mt * 16 + g) * AS_STR + kk + tg];
                af[mt][0] = f2tf(sp[0]);
                af[mt][1] = f2tf(sp[8 * AS_STR]);
                af[mt][2] = f2tf(sp[4]);
                af[mt][3] = f2tf(sp[8 * AS_STR + 4]);
            }
            #pragma unroll
            for (int nt = 0; nt < 4; nt++) {
                const float* sp = &Bb[(kk + tg) * BS_STR + wn + nt * 8 + g];
                bf[nt][0] = f2tf(sp[0]);
                bf[nt][1] = f2tf(sp[4 * BS_STR]);
            }
            #pragma unroll
            for (int mt = 0; mt < 4; mt++)
                #pragma unroll
                for (int nt = 0; nt < 4; nt++)
                    mma8(acc[mt][nt], af[mt], bf[nt]);
        }
        __syncthreads();
    }

    #pragma unroll
    for (int mt = 0; mt < 4; mt++) {
        const int row = by * 128 + wm + mt * 16 + g;
        #pragma unroll
        for (int nt = 0; nt < 4; nt++) {
            const int col = colb + wn + nt * 8 + tg * 2;
            const float b0 = bias[col], b1 = bias[col + 1];
            *(float2*)(C + (size_t)row * N + col) =
                make_float2(acc[mt][nt][0] + b0, acc[mt][nt][1] + b1);
            *(float2*)(C + (size_t)(row + 8) * N + col) =
                make_float2(acc[mt][nt][2] + b0, acc[mt][nt][3] + b1);
        }
    }
}

// Fused QKV projection: bx 0..15 -> Wq, 16..19 -> Wk, 20..23 -> Wv
__global__ __launch_bounds__(256)
void gemm_qkv(const float* __restrict__ x,
              const float* __restrict__ Wq, const float* __restrict__ bq,
              const float* __restrict__ Wk, const float* __restrict__ bk,
              const float* __restrict__ Wv, const float* __restrict__ bv,
              float* __restrict__ Qo, float* __restrict__ Ko, float* __restrict__ Vo)
{
    const int bx = blockIdx.x;
    const float* B; const float* bias; float* C; int N, colb;
    if (bx < 16)      { B = Wq; bias = bq; C = Qo; N = D_MODEL; colb = bx * 128; }
    else if (bx < 20) { B = Wk; bias = bk; C = Ko; N = KV_DIM;  colb = (bx - 16) * 128; }
    else              { B = Wv; bias = bv; C = Vo; N = KV_DIM;  colb = (bx - 20) * 128; }
    gemm_core(x, B, bias, C, N, D_MODEL, colb, blockIdx.y);
}

__global__ __launch_bounds__(256)
void gemm_o(const float* __restrict__ A, const float* __restrict__ B,
            const float* __restrict__ bias, float* __restrict__ C)
{
    gemm_core(A, B, bias, C, D_MODEL, D_MODEL, blockIdx.x * 128, blockIdx.y);
}

// ---------------------------------------------------------------------------
// Flash attention, tf32 MMA, cp.async double-buffered K/V (raw fp32, converted
// in place once per tile), 128 queries per CTA, 8 warps (16 rows each).
// ---------------------------------------------------------------------------
#define KS_STR 68
#define VS_STR 72
#define PS_STR 68
#define K_STAGE (64 * KS_STR)
#define V_STAGE (64 * VS_STR)
#define ATTN_SMEM_BYTES ((2 * K_STAGE + 2 * V_STAGE + 128 * PS_STR) * 4)

__global__ __launch_bounds__(256)
void attn_tf32(const float* __restrict__ Q, const float* __restrict__ K,
               const float* __restrict__ V, float* __restrict__ C)
{
    extern __shared__ float sm[];
    float* Ks = sm;                            // [2][64][KS_STR] raw->tf32
    float* Vs = sm + 2 * K_STAGE;              // [2][64][VS_STR]
    float* QP = Vs + 2 * V_STAGE;              // [128][PS_STR] Q tf32 / P buffer
    const uint32_t ks_u = (uint32_t)__cvta_generic_to_shared(Ks);
    const uint32_t vs_u = (uint32_t)__cvta_generic_to_shared(Vs);

    const int tid  = threadIdx.x;
    const int lane = tid & 31;
    const int wid  = tid >> 5;                 // 0..7
    const int g    = lane >> 2;
    const int tg   = lane & 3;
    const int r0   = wid * 16;

    const int qt = blockIdx.x;                 // 128-query tile
    const int h  = blockIdx.y;
    const int b  = blockIdx.z;
    const int hkv = h >> 2;

    auto issueKV = [&](int st, int kt) {
        #pragma unroll
        for (int p = 0; p < 4; p++) {
            int idx = p * 256 + tid;
            int j = idx >> 4, c = (idx & 15) << 2;
            const size_t go = (size_t)(b * SEQ + kt * 64 + j) * KV_DIM + hkv * HDIM + c;
            cpa16(ks_u + (uint32_t)(st * K_STAGE + j * KS_STR + c) * 4, K + go);
            cpa16(vs_u + (uint32_t)(st * V_STAGE + j * VS_STR + c) * 4, V + go);
        }
    };

    issueKV(0, 0);
    cpa_commit();

    // Stage Q (scaled, tf32) into QP[r][d]
    #pragma unroll
    for (int p = 0; p < 8; p++) {
        int idx = p * 256 + tid;
        int r = idx >> 4, c4 = (idx & 15) << 2;
        float4 q4 = *(const float4*)(Q + (size_t)(b * SEQ + qt * 128 + r) * D_MODEL
                                       + h * HDIM + c4);
        *(float4*)&QP[r * PS_STR + c4] =
            make_float4(f2tff(q4.x * 0.125f), f2tff(q4.y * 0.125f),
                        f2tff(q4.z * 0.125f), f2tff(q4.w * 0.125f));
    }
    __syncthreads();

    unsigned aQ[8][4];
    #pragma unroll
    for (int gk = 0; gk < 8; gk++) {
        const float* sp = &QP[(r0 + g) * PS_STR + gk * 8 + tg];
        aQ[gk][0] = __float_as_uint(sp[0]);
        aQ[gk][1] = __float_as_uint(sp[8 * PS_STR]);
        aQ[gk][2] = __float_as_uint(sp[4]);
        aQ[gk][3] = __float_as_uint(sp[8 * PS_STR + 4]);
    }

    float o[8][4];
    #pragma unroll
    for (int nt = 0; nt < 8; nt++)
        #pragma unroll
        for (int i = 0; i < 4; i++) o[nt][i] = 0.f;
    float m0 = -1e30f, m1 = -1e30f, l0 = 0.f, l1 = 0.f;

    for (int kt = 0; kt < SEQ / 64; kt++) {
        if (kt + 1 < SEQ / 64) {
            issueKV((kt + 1) & 1, kt + 1);
            cpa_commit();
            cpa_wait<1>();
        } else {
            cpa_wait<0>();
        }
        __syncthreads();

        float* Kb = Ks + (kt & 1) * K_STAGE;
        float* Vb = Vs + (kt & 1) * V_STAGE;

        // In-place fp32 -> tf32 conversion (each element once)
        for (int i = tid; i < K_STAGE / 4; i += 256) {
            float4 v = *(float4*)(Kb + 4 * i);
            *(float4*)(Kb + 4 * i) =
                make_float4(f2tff(v.x), f2tff(v.y), f2tff(v.z), f2tff(v.w));
        }
        for (int i = tid; i < V_STAGE / 4; i += 256) {
            float4 v = *(float4*)(Vb + 4 * i);
            *(float4*)(Vb + 4 * i) =
                make_float4(f2tff(v.x), f2tff(v.y), f2tff(v.z), f2tff(v.w));
        }
        __syncthreads();

        // S = Q @ K^T
        float s[8][4];
        #pragma unroll
        for (int nt = 0; nt < 8; nt++)
            #pragma unroll
            for (int i = 0; i < 4; i++) s[nt][i] = 0.f;

        #pragma unroll
        for (int gk = 0; gk < 8; gk++) {
            #pragma unroll
            for (int nt = 0; nt < 8; nt++) {
                unsigned bk[2];
                const float* kb = &Kb[(nt * 8 + g) * KS_STR + gk * 8 + tg];
                bk[0] = __float_as_uint(kb[0]);
                bk[1] = __float_as_uint(kb[4]);
                mma8(s[nt], aQ[gk], bk);
            }
        }

        // Online softmax (rows r0+g and r0+g+8)
        float tm0 = -1e30f, tm1 = -1e30f;
        #pragma unroll
        for (int nt = 0; nt < 8; nt++) {
            tm0 = fmaxf(tm0, fmaxf(s[nt][0], s[nt][1]));
            tm1 = fmaxf(tm1, fmaxf(s[nt][2], s[nt][3]));
        }
        tm0 = fmaxf(tm0, __shfl_xor_sync(0xffffffffu, tm0, 1));
        tm0 = fmaxf(tm0, __shfl_xor_sync(0xffffffffu, tm0, 2));
        tm1 = fmaxf(tm1, __shfl_xor_sync(0xffffffffu, tm1, 1));
        tm1 = fmaxf(tm1, __shfl_xor_sync(0xffffffffu, tm1, 2));

        float nm0 = fmaxf(m0, tm0), nm1 = fmaxf(m1, tm1);
        float c0 = __expf(m0 - nm0), c1 = __expf(m1 - nm1);
        m0 = nm0; m1 = nm1;

        float rs0 = 0.f, rs1 = 0.f;
        #pragma unroll
        for (int nt = 0; nt < 8; nt++) {
            float p0 = __expf(s[nt][0] - m0);
            float p1 = __expf(s[nt][1] - m0);
            float p2 = __expf(s[nt][2] - m1);
            float p3 = __expf(s[nt][3] - m1);
            rs0 += p0 + p1;
            rs1 += p2 + p3;
            *(float2*)&QP[(r0 + g) * PS_STR + nt * 8 + tg * 2] =
                make_float2(f2tff(p0), f2tff(p1));
            *(float2*)&QP[(r0 + g + 8) * PS_STR + nt * 8 + tg * 2] =
                make_float2(f2tff(p2), f2tff(p3));
            o[nt][0] *= c0; o[nt][1] *= c0;
            o[nt][2] *= c1; o[nt][3] *= c1;
        }
        rs0 += __shfl_xor_sync(0xffffffffu, rs0, 1);
        rs0 += __shfl_xor_sync(0xffffffffu, rs0, 2);
        rs1 += __shfl_xor_sync(0xffffffffu, rs1, 1);
        rs1 += __shfl_xor_sync(0xffffffffu, rs1, 2);
        l0 = l0 * c0 + rs0;
        l1 = l1 * c1 + rs1;
        __syncwarp();

        // O += P @ V
        #pragma unroll
        for (int gk = 0; gk < 8; gk++) {
            unsigned aP[4];
            const float* pb = &QP[(r0 + g) * PS_STR + gk * 8 + tg];
            aP[0] = __float_as_uint(pb[0]);
            aP[1] = __float_as_uint(pb[8 * PS_STR]);
            aP[2] = __float_as_uint(pb[4]);
            aP[3] = __float_as_uint(pb[8 * PS_STR + 4]);
            #pragma unroll
            for (int nt = 0; nt < 8; nt++) {
                unsigned bv[2];
                const float* vb = &Vb[(gk * 8 + tg) * VS_STR + nt * 8 + g];
                bv[0] = __float_as_uint(vb[0]);
                bv[1] = __float_as_uint(vb[4 * VS_STR]);
                mma8(o[nt], aP, bv);
            }
        }
        __syncthreads();   // stage fully consumed before next issue overwrites
    }

    const float i0 = 1.f / l0, i1 = 1.f / l1;
    #pragma unroll
    for (int nt = 0; nt < 8; nt++) {
        const size_t row = (size_t)(b * SEQ + qt * 128 + r0 + g);
        const int col = h * HDIM + nt * 8 + tg * 2;
        *(float2*)(C + row * D_MODEL + col) =
            make_float2(o[nt][0] * i0, o[nt][1] * i0);
        *(float2*)(C + (row + 8) * D_MODEL + col) =
            make_float2(o[nt][2] * i1, o[nt][3] * i1);
    }
}

// ---------------------------------------------------------------------------
// Launch
// ---------------------------------------------------------------------------
extern "C" void kernel_launch(void* const* d_in, const int* in_sizes, int n_in,
                              void* d_out, int out_size)
{
    const float* x  = (const float*)d_in[0];
    const float* Wq = (const float*)d_in[1];
    const float* bq = (const float*)d_in[2];
    const float* Wk = (const float*)d_in[3];
    const float* bk = (const float*)d_in[4];
    const float* Wv = (const float*)d_in[5];
    const float* bv = (const float*)d_in[6];
    const float* Wo = (const float*)d_in[7];
    const float* bo = (const float*)d_in[8];
    float* out = (float*)d_out;

    float *pQ, *pK, *pV, *pC;
    cudaGetSymbolAddress((void**)&pQ, g_Q);
    cudaGetSymbolAddress((void**)&pK, g_K);
    cudaGetSymbolAddress((void**)&pV, g_V);
    cudaGetSymbolAddress((void**)&pC, g_C);

    cudaFuncSetAttribute(gemm_qkv, cudaFuncAttributeMaxDynamicSharedMemorySize, GEMM_SMEM_BYTES);
    cudaFuncSetAttribute(gemm_o,   cudaFuncAttributeMaxDynamicSharedMemorySize, GEMM_SMEM_BYTES);
    cudaFuncSetAttribute(attn_tf32, cudaFuncAttributeMaxDynamicSharedMemorySize, ATTN_SMEM_BYTES);

    // Fused QKV projection
    gemm_qkv<<<dim3(24, MTOK / 128), 256, GEMM_SMEM_BYTES>>>(
        x, Wq, bq, Wk, bk, Wv, bv, pQ, pK, pV);

    // Attention
    attn_tf32<<<dim3(SEQ / 128, HEADS, BATCH), 256, ATTN_SMEM_BYTES>>>(pQ, pK, pV, pC);

    // Output projection
    gemm_o<<<dim3(D_MODEL / 128, MTOK / 128), 256, GEMM_SMEM_BYTES>>>(pC, Wo, bo, out);
}

// round 5
// speedup vs baseline: 4.1733x; 1.0848x over previous
#include <cuda_runtime.h>
#include <cstdint>

#define D_MODEL 2048
#define KV_DIM  512
#define BATCH   2
#define SEQ     2048
#define MTOK    4096
#define HEADS   32
#define HDIM    64

// Scratch (device globals: no allocations allowed)
__device__ float g_X [(size_t)MTOK * D_MODEL];    // tf32-rounded x
__device__ float g_Wq[(size_t)D_MODEL * D_MODEL]; // tf32-rounded weights
__device__ float g_Wk[(size_t)D_MODEL * KV_DIM];
__device__ float g_Wv[(size_t)D_MODEL * KV_DIM];
__device__ float g_Wo[(size_t)D_MODEL * D_MODEL];
__device__ float g_Q [(size_t)MTOK * D_MODEL];    // tf32-rounded projections
__device__ float g_K [(size_t)MTOK * KV_DIM];
__device__ float g_V [(size_t)MTOK * KV_DIM];
__device__ float g_C [(size_t)MTOK * D_MODEL];    // tf32-rounded context

// ---------------------------------------------------------------------------
// helpers
// ---------------------------------------------------------------------------
__device__ __forceinline__ unsigned f2tf(float x) {
    unsigned u;
    asm("cvt.rna.tf32.f32 %0, %1;" : "=r"(u) : "f"(x));
    return u;
}
__device__ __forceinline__ float f2tff(float x) { return __uint_as_float(f2tf(x)); }

__device__ __forceinline__ void mma8(float* d, const unsigned* a, const unsigned* b) {
    asm volatile(
        "mma.sync.aligned.m16n8k8.row.col.f32.tf32.tf32.f32 "
        "{%0,%1,%2,%3},{%4,%5,%6,%7},{%8,%9},{%0,%1,%2,%3};"
        : "+f"(d[0]), "+f"(d[1]), "+f"(d[2]), "+f"(d[3])
        : "r"(a[0]), "r"(a[1]), "r"(a[2]), "r"(a[3]), "r"(b[0]), "r"(b[1]));
}

__device__ __forceinline__ void cpa16(uint32_t dst, const void* src) {
    asm volatile("cp.async.cg.shared.global [%0], [%1], 16;" :: "r"(dst), "l"(src));
}
__device__ __forceinline__ void cpa_commit() {
    asm volatile("cp.async.commit_group;");
}
template <int N>
__device__ __forceinline__ void cpa_wait() {
    asm volatile("cp.async.wait_group %0;" :: "n"(N));
}

// ---------------------------------------------------------------------------
// Pre-pass: elementwise tf32-RNA rounding
// ---------------------------------------------------------------------------
__global__ __launch_bounds__(256)
void cvt_tf32_kernel(const float4* __restrict__ in, float4* __restrict__ out) {
    int i = blockIdx.x * 256 + threadIdx.x;
    float4 v = in[i];
    out[i] = make_float4(f2tff(v.x), f2tff(v.y), f2tff(v.z), f2tff(v.w));
}

// ---------------------------------------------------------------------------
// tf32 GEMM: C[M,N] = A[M,K] @ B[K,N] + bias. Operands pre-rounded to tf32 ->
// no cvt in the inner loop. CTA 128x128, K-step 32, 2-stage cp.async,
// 8 warps x (64x32). roundC: round outputs (for Q/K/V feeding later MMAs).
// ---------------------------------------------------------------------------
#define AS_STR 36
#define BS_STR 136
#define A_STAGE (128 * AS_STR)
#define B_STAGE (32 * BS_STR)
#define GEMM_SMEM_BYTES ((2 * A_STAGE + 2 * B_STAGE) * 4)

__device__ __forceinline__ void gemm_core(
    const float* __restrict__ A, const float* __restrict__ B,
    const float* __restrict__ bias, float* __restrict__ C,
    int N, int K, int colb, int by, int roundC)
{
    extern __shared__ float sm[];
    float* As = sm;
    float* Bs = sm + 2 * A_STAGE;
    const uint32_t as_u = (uint32_t)__cvta_generic_to_shared(As);
    const uint32_t bs_u = (uint32_t)__cvta_generic_to_shared(Bs);

    const int tid  = threadIdx.x;
    const int lane = tid & 31;
    const int wid  = tid >> 5;
    const int wm = (wid >> 2) * 64;
    const int wn = (wid & 3) * 32;
    const int g  = lane >> 2;
    const int tg = lane & 3;

    float acc[4][4][4];
    #pragma unroll
    for (int mt = 0; mt < 4; mt++)
        #pragma unroll
        for (int nt = 0; nt < 4; nt++)
            #pragma unroll
            for (int i = 0; i < 4; i++) acc[mt][nt][i] = 0.f;

    auto issue = [&](int st, int k0) {
        #pragma unroll
        for (int p = 0; p < 4; p++) {          // A tile 128x32
            int idx = p * 256 + tid;
            int r = idx >> 3, c = (idx & 7) << 2;
            cpa16(as_u + (uint32_t)(st * A_STAGE + r * AS_STR + c) * 4,
                  A + (size_t)(by * 128 + r) * K + k0 + c);
        }
        #pragma unroll
        for (int p = 0; p < 4; p++) {          // B tile 32x128
            int idx = p * 256 + tid;
            int r = idx >> 5, c = (idx & 31) << 2;
            cpa16(bs_u + (uint32_t)(st * B_STAGE + r * BS_STR + c) * 4,
                  B + (size_t)(k0 + r) * N + colb + c);
        }
    };

    const int nsteps = K / 32;
    issue(0, 0);
    cpa_commit();

    for (int s = 0; s < nsteps; s++) {
        if (s + 1 < nsteps) {
            issue((s + 1) & 1, (s + 1) * 32);
            cpa_commit();
            cpa_wait<1>();
        } else {
            cpa_wait<0>();
        }
        __syncthreads();

        const float* Ab = As + (s & 1) * A_STAGE;
        const float* Bb = Bs + (s & 1) * B_STAGE;

        #pragma unroll
        for (int kk = 0; kk < 32; kk += 8) {
            unsigned af[4][4], bf[4][2];
            #pragma unroll
            for (int mt = 0; mt < 4; mt++) {
                const float* sp = &Ab[(wm + mt * 16 + g) * AS_STR + kk + tg];
                af[mt][0] = __float_as_uint(sp[0]);
                af[mt][1] = __float_as_uint(sp[8 * AS_STR]);
                af[mt][2] = __float_as_uint(sp[4]);
                af[mt][3] = __float_as_uint(sp[8 * AS_STR + 4]);
            }
            #pragma unroll
            for (int nt = 0; nt < 4; nt++) {
                const float* sp = &Bb[(kk + tg) * BS_STR + wn + nt * 8 + g];
                bf[nt][0] = __float_as_uint(sp[0]);
                bf[nt][1] = __float_as_uint(sp[4 * BS_STR]);
            }
            #pragma unroll
            for (int mt = 0; mt < 4; mt++)
                #pragma unroll
                for (int nt = 0; nt < 4; nt++)
                    mma8(acc[mt][nt], af[mt], bf[nt]);
        }
        __syncthreads();
    }

    #pragma unroll
    for (int mt = 0; mt < 4; mt++) {
        const int row = by * 128 + wm + mt * 16 + g;
        #pragma unroll
        for (int nt = 0; nt < 4; nt++) {
            const int col = colb + wn + nt * 8 + tg * 2;
            const float b0 = bias[col], b1 = bias[col + 1];
            float v0 = acc[mt][nt][0] + b0, v1 = acc[mt][nt][1] + b1;
            float v2 = acc[mt][nt][2] + b0, v3 = acc[mt][nt][3] + b1;
            if (roundC) {
                v0 = f2tff(v0); v1 = f2tff(v1);
                v2 = f2tff(v2); v3 = f2tff(v3);
            }
            *(float2*)(C + (size_t)row * N + col) = make_float2(v0, v1);
            *(float2*)(C + (size_t)(row + 8) * N + col) = make_float2(v2, v3);
        }
    }
}

// Fused QKV projection: bx 0..15 -> Wq, 16..19 -> Wk, 20..23 -> Wv
__global__ __launch_bounds__(256)
void gemm_qkv(const float* __restrict__ x,
              const float* __restrict__ Wq, const float* __restrict__ bq,
              const float* __restrict__ Wk, const float* __restrict__ bk,
              const float* __restrict__ Wv, const float* __restrict__ bv,
              float* __restrict__ Qo, float* __restrict__ Ko, float* __restrict__ Vo)
{
    const int bx = blockIdx.x;
    const float* B; const float* bias; float* C; int N, colb;
    if (bx < 16)      { B = Wq; bias = bq; C = Qo; N = D_MODEL; colb = bx * 128; }
    else if (bx < 20) { B = Wk; bias = bk; C = Ko; N = KV_DIM;  colb = (bx - 16) * 128; }
    else              { B = Wv; bias = bv; C = Vo; N = KV_DIM;  colb = (bx - 20) * 128; }
    gemm_core(x, B, bias, C, N, D_MODEL, colb, blockIdx.y, 1);
}

__global__ __launch_bounds__(256)
void gemm_o(const float* __restrict__ A, const float* __restrict__ B,
            const float* __restrict__ bias, float* __restrict__ C)
{
    gemm_core(A, B, bias, C, D_MODEL, D_MODEL, blockIdx.x * 128, blockIdx.y, 0);
}

// ---------------------------------------------------------------------------
// Flash attention, tf32 MMA. 4 warps/CTA, each warp owns 32 query rows
// (two 16-row MMA blocks) -> every K/V fragment LDS feeds 2 MMAs.
// K/V/Q arrive pre-rounded to tf32 (GEMM epilogue), so no cvt except on P.
// ---------------------------------------------------------------------------
#define KS_STR 68
#define VS_STR 72
#define PS_STR 68
#define K_STAGE (64 * KS_STR)
#define V_STAGE (64 * VS_STR)
#define ATTN_SMEM_BYTES ((2 * K_STAGE + 2 * V_STAGE + 128 * PS_STR) * 4)

__global__ __launch_bounds__(128)
void attn_tf32(const float* __restrict__ Q, const float* __restrict__ K,
               const float* __restrict__ V, float* __restrict__ C)
{
    extern __shared__ float sm[];
    float* Ks = sm;                            // [2][64][KS_STR]
    float* Vs = sm + 2 * K_STAGE;              // [2][64][VS_STR]
    float* QP = Vs + 2 * V_STAGE;              // [128][PS_STR] Q stage / P buffer
    const uint32_t ks_u = (uint32_t)__cvta_generic_to_shared(Ks);
    const uint32_t vs_u = (uint32_t)__cvta_generic_to_shared(Vs);

    const int tid  = threadIdx.x;
    const int lane = tid & 31;
    const int wid  = tid >> 5;                 // 0..3
    const int g    = lane >> 2;
    const int tg   = lane & 3;
    const int rA   = wid * 32;                 // block 0 rows [rA, rA+16)
    const int rB   = rA + 16;                  // block 1 rows [rB, rB+16)

    const int qt = blockIdx.x;                 // 128-query tile
    const int h  = blockIdx.y;
    const int b  = blockIdx.z;
    const int hkv = h >> 2;

    auto issueKV = [&](int st, int kt) {
        #pragma unroll
        for (int p = 0; p < 8; p++) {
            int idx = p * 128 + tid;
            int j = idx >> 4, c = (idx & 15) << 2;
            const size_t go = (size_t)(b * SEQ + kt * 64 + j) * KV_DIM + hkv * HDIM + c;
            cpa16(ks_u + (uint32_t)(st * K_STAGE + j * KS_STR + c) * 4, K + go);
            cpa16(vs_u + (uint32_t)(st * V_STAGE + j * VS_STR + c) * 4, V + go);
        }
    };

    issueKV(0, 0);
    cpa_commit();

    // Stage Q (x0.125 exact; Q already tf32-rounded)
    #pragma unroll
    for (int p = 0; p < 16; p++) {
        int idx = p * 128 + tid;
        int r = idx >> 4, c4 = (idx & 15) << 2;
        float4 q4 = *(const float4*)(Q + (size_t)(b * SEQ + qt * 128 + r) * D_MODEL
                                       + h * HDIM + c4);
        *(float4*)&QP[r * PS_STR + c4] =
            make_float4(q4.x * 0.125f, q4.y * 0.125f, q4.z * 0.125f, q4.w * 0.125f);
    }
    __syncthreads();

    unsigned aQ[2][8][4];
    #pragma unroll
    for (int bl = 0; bl < 2; bl++) {
        const int r0 = bl ? rB : rA;
        #pragma unroll
        for (int gk = 0; gk < 8; gk++) {
            const float* sp = &QP[(r0 + g) * PS_STR + gk * 8 + tg];
            aQ[bl][gk][0] = __float_as_uint(sp[0]);
            aQ[bl][gk][1] = __float_as_uint(sp[8 * PS_STR]);
            aQ[bl][gk][2] = __float_as_uint(sp[4]);
            aQ[bl][gk][3] = __float_as_uint(sp[8 * PS_STR + 4]);
        }
    }

    float o[2][8][4];
    #pragma unroll
    for (int bl = 0; bl < 2; bl++)
        #pragma unroll
        for (int nt = 0; nt < 8; nt++)
            #pragma unroll
            for (int i = 0; i < 4; i++) o[bl][nt][i] = 0.f;
    float m[2][2] = {{-1e30f, -1e30f}, {-1e30f, -1e30f}};
    float l[2][2] = {{0.f, 0.f}, {0.f, 0.f}};

    for (int kt = 0; kt < SEQ / 64; kt++) {
        if (kt + 1 < SEQ / 64) {
            issueKV((kt + 1) & 1, kt + 1);
            cpa_commit();
            cpa_wait<1>();
        } else {
            cpa_wait<0>();
        }
        __syncthreads();

        const float* Kb = Ks + (kt & 1) * K_STAGE;
        const float* Vb = Vs + (kt & 1) * V_STAGE;

        // S = Q @ K^T : each K fragment feeds both row-blocks
        float s[2][8][4];
        #pragma unroll
        for (int bl = 0; bl < 2; bl++)
            #pragma unroll
            for (int nt = 0; nt < 8; nt++)
                #pragma unroll
                for (int i = 0; i < 4; i++) s[bl][nt][i] = 0.f;

        #pragma unroll
        for (int gk = 0; gk < 8; gk++) {
            #pragma unroll
            for (int nt = 0; nt < 8; nt++) {
                unsigned bk[2];
                const float* kb = &Kb[(nt * 8 + g) * KS_STR + gk * 8 + tg];
                bk[0] = __float_as_uint(kb[0]);
                bk[1] = __float_as_uint(kb[4]);
                mma8(s[0][nt], aQ[0][gk], bk);
                mma8(s[1][nt], aQ[1][gk], bk);
            }
        }

        // Online softmax per block (thread: rows r0+g via c0/c1, r0+g+8 via c2/c3)
        #pragma unroll
        for (int bl = 0; bl < 2; bl++) {
            const int r0 = bl ? rB : rA;
            float tm0 = -1e30f, tm1 = -1e30f;
            #pragma unroll
            for (int nt = 0; nt < 8; nt++) {
                tm0 = fmaxf(tm0, fmaxf(s[bl][nt][0], s[bl][nt][1]));
                tm1 = fmaxf(tm1, fmaxf(s[bl][nt][2], s[bl][nt][3]));
            }
            tm0 = fmaxf(tm0, __shfl_xor_sync(0xffffffffu, tm0, 1));
            tm0 = fmaxf(tm0, __shfl_xor_sync(0xffffffffu, tm0, 2));
            tm1 = fmaxf(tm1, __shfl_xor_sync(0xffffffffu, tm1, 1));
            tm1 = fmaxf(tm1, __shfl_xor_sync(0xffffffffu, tm1, 2));

            float nm0 = fmaxf(m[bl][0], tm0), nm1 = fmaxf(m[bl][1], tm1);
            float c0 = __expf(m[bl][0] - nm0), c1 = __expf(m[bl][1] - nm1);
            m[bl][0] = nm0; m[bl][1] = nm1;

            float rs0 = 0.f, rs1 = 0.f;
            #pragma unroll
            for (int nt = 0; nt < 8; nt++) {
                float p0 = __expf(s[bl][nt][0] - nm0);
                float p1 = __expf(s[bl][nt][1] - nm0);
                float p2 = __expf(s[bl][nt][2] - nm1);
                float p3 = __expf(s[bl][nt][3] - nm1);
                rs0 += p0 + p1;
                rs1 += p2 + p3;
                *(float2*)&QP[(r0 + g) * PS_STR + nt * 8 + tg * 2] =
                    make_float2(f2tff(p0), f2tff(p1));
                *(float2*)&QP[(r0 + g + 8) * PS_STR + nt * 8 + tg * 2] =
                    make_float2(f2tff(p2), f2tff(p3));
                o[bl][nt][0] *= c0; o[bl][nt][1] *= c0;
                o[bl][nt][2] *= c1; o[bl][nt][3] *= c1;
            }
            rs0 += __shfl_xor_sync(0xffffffffu, rs0, 1);
            rs0 += __shfl_xor_sync(0xffffffffu, rs0, 2);
            rs1 += __shfl_xor_sync(0xffffffffu, rs1, 1);
            rs1 += __shfl_xor_sync(0xffffffffu, rs1, 2);
            l[bl][0] = l[bl][0] * c0 + rs0;
            l[bl][1] = l[bl][1] * c1 + rs1;
        }
        __syncwarp();

        // O += P @ V : each V fragment feeds both row-blocks
        #pragma unroll
        for (int gk = 0; gk < 8; gk++) {
            unsigned aP0[4], aP1[4];
            const float* p0 = &QP[(rA + g) * PS_STR + gk * 8 + tg];
            aP0[0] = __float_as_uint(p0[0]);
            aP0[1] = __float_as_uint(p0[8 * PS_STR]);
            aP0[2] = __float_as_uint(p0[4]);
            aP0[3] = __float_as_uint(p0[8 * PS_STR + 4]);
            const float* p1 = &QP[(rB + g) * PS_STR + gk * 8 + tg];
            aP1[0] = __float_as_uint(p1[0]);
            aP1[1] = __float_as_uint(p1[8 * PS_STR]);
            aP1[2] = __float_as_uint(p1[4]);
            aP1[3] = __float_as_uint(p1[8 * PS_STR + 4]);
            #pragma unroll
            for (int nt = 0; nt < 8; nt++) {
                unsigned bv[2];
                const float* vb = &Vb[(gk * 8 + tg) * VS_STR + nt * 8 + g];
                bv[0] = __float_as_uint(vb[0]);
                bv[1] = __float_as_uint(vb[4 * VS_STR]);
                mma8(o[0][nt], aP0, bv);
                mma8(o[1][nt], aP1, bv);
            }
        }
        __syncthreads();   // all warps done with this stage before overwrite
    }

    // Normalize and write context (tf32-rounded for the O projection)
    #pragma unroll
    for (int bl = 0; bl < 2; bl++) {
        const int r0 = bl ? rB : rA;
        const float i0 = 1.f / l[bl][0], i1 = 1.f / l[bl][1];
        #pragma unroll
        for (int nt = 0; nt < 8; nt++) {
            const size_t row = (size_t)(b * SEQ + qt * 128 + r0 + g);
            const int col = h * HDIM + nt * 8 + tg * 2;
            *(float2*)(C + row * D_MODEL + col) =
                make_float2(f2tff(o[bl][nt][0] * i0), f2tff(o[bl][nt][1] * i0));
            *(float2*)(C + (row + 8) * D_MODEL + col) =
                make_float2(f2tff(o[bl][nt][2] * i1), f2tff(o[bl][nt][3] * i1));
        }
    }
}

// ---------------------------------------------------------------------------
// Launch
// ---------------------------------------------------------------------------
extern "C" void kernel_launch(void* const* d_in, const int* in_sizes, int n_in,
                              void* d_out, int out_size)
{
    const float* x  = (const float*)d_in[0];
    const float* Wq = (const float*)d_in[1];
    const float* bq = (const float*)d_in[2];
    const float* Wk = (const float*)d_in[3];
    const float* bk = (const float*)d_in[4];
    const float* Wv = (const float*)d_in[5];
    const float* bv = (const float*)d_in[6];
    const float* Wo = (const float*)d_in[7];
    const float* bo = (const float*)d_in[8];
    float* out = (float*)d_out;

    float *pX, *pWq, *pWk, *pWv, *pWo, *pQ, *pK, *pV, *pC;
    cudaGetSymbolAddress((void**)&pX, g_X);
    cudaGetSymbolAddress((void**)&pWq, g_Wq);
    cudaGetSymbolAddress((void**)&pWk, g_Wk);
    cudaGetSymbolAddress((void**)&pWv, g_Wv);
    cudaGetSymbolAddress((void**)&pWo, g_Wo);
    cudaGetSymbolAddress((void**)&pQ, g_Q);
    cudaGetSymbolAddress((void**)&pK, g_K);
    cudaGetSymbolAddress((void**)&pV, g_V);
    cudaGetSymbolAddress((void**)&pC, g_C);

    cudaFuncSetAttribute(gemm_qkv, cudaFuncAttributeMaxDynamicSharedMemorySize, GEMM_SMEM_BYTES);
    cudaFuncSetAttribute(gemm_o,   cudaFuncAttributeMaxDynamicSharedMemorySize, GEMM_SMEM_BYTES);
    cudaFuncSetAttribute(attn_tf32, cudaFuncAttributeMaxDynamicSharedMemorySize, ATTN_SMEM_BYTES);

    // Pre-pass: tf32-RNA rounding of activations + weights
    cvt_tf32_kernel<<<(MTOK * D_MODEL / 4) / 256, 256>>>((const float4*)x,  (float4*)pX);
    cvt_tf32_kernel<<<(D_MODEL * D_MODEL / 4) / 256, 256>>>((const float4*)Wq, (float4*)pWq);
    cvt_tf32_kernel<<<(D_MODEL * KV_DIM  / 4) / 256, 256>>>((const float4*)Wk, (float4*)pWk);
    cvt_tf32_kernel<<<(D_MODEL * KV_DIM  / 4) / 256, 256>>>((const float4*)Wv, (float4*)pWv);
    cvt_tf32_kernel<<<(D_MODEL * D_MODEL / 4) / 256, 256>>>((const float4*)Wo, (float4*)pWo);

    // Fused QKV projection (outputs tf32-rounded)
    gemm_qkv<<<dim3(24, MTOK / 128), 256, GEMM_SMEM_BYTES>>>(
        pX, pWq, bq, pWk, bk, pWv, bv, pQ, pK, pV);

    // Attention
    attn_tf32<<<dim3(SEQ / 128, HEADS, BATCH), 128, ATTN_SMEM_BYTES>>>(pQ, pK, pV, pC);

    // Output projection (raw fp32 output)
    gemm_o<<<dim3(D_MODEL / 128, MTOK / 128), 256, GEMM_SMEM_BYTES>>>(pC, pWo, bo, out);
}

// round 7
// speedup vs baseline: 4.1761x; 1.0007x over previous
#include <cuda_runtime.h>
#include <cstdint>

#define D_MODEL 2048
#define KV_DIM  512
#define BATCH   2
#define SEQ     2048
#define MTOK    4096
#define HEADS   32
#define HDIM    64

// Scratch (device globals: no allocations allowed)
__device__ float g_X [(size_t)MTOK * D_MODEL];
__device__ float g_Wq[(size_t)D_MODEL * D_MODEL];
__device__ float g_Wk[(size_t)D_MODEL * KV_DIM];
__device__ float g_Wv[(size_t)D_MODEL * KV_DIM];
__device__ float g_Wo[(size_t)D_MODEL * D_MODEL];
__device__ float g_Q [(size_t)MTOK * D_MODEL];
__device__ float g_K [(size_t)MTOK * KV_DIM];
__device__ float g_V [(size_t)MTOK * KV_DIM];
__device__ float g_C [(size_t)MTOK * D_MODEL];

// ---------------------------------------------------------------------------
// helpers
// ---------------------------------------------------------------------------
__device__ __forceinline__ unsigned f2tf(float x) {
    unsigned u;
    asm("cvt.rna.tf32.f32 %0, %1;" : "=r"(u) : "f"(x));
    return u;
}
__device__ __forceinline__ float f2tff(float x) { return __uint_as_float(f2tf(x)); }

__device__ __forceinline__ float ex2(float x) {
    float r;
    asm("ex2.approx.f32 %0, %1;" : "=f"(r) : "f"(x));
    return r;
}

__device__ __forceinline__ void mma8(float* d, const unsigned* a, const unsigned* b) {
    asm volatile(
        "mma.sync.aligned.m16n8k8.row.col.f32.tf32.tf32.f32 "
        "{%0,%1,%2,%3},{%4,%5,%6,%7},{%8,%9},{%0,%1,%2,%3};"
        : "+f"(d[0]), "+f"(d[1]), "+f"(d[2]), "+f"(d[3])
        : "r"(a[0]), "r"(a[1]), "r"(a[2]), "r"(a[3]), "r"(b[0]), "r"(b[1]));
}

__device__ __forceinline__ void cpa16(uint32_t dst, const void* src) {
    asm volatile("cp.async.cg.shared.global [%0], [%1], 16;" :: "r"(dst), "l"(src));
}
__device__ __forceinline__ void cpa_commit() {
    asm volatile("cp.async.commit_group;");
}
template <int N>
__device__ __forceinline__ void cpa_wait() {
    asm volatile("cp.async.wait_group %0;" :: "n"(N));
}

// ---------------------------------------------------------------------------
// Pre-pass: elementwise tf32-RNA rounding
// ---------------------------------------------------------------------------
__global__ __launch_bounds__(256)
void cvt_tf32_kernel(const float4* __restrict__ in, float4* __restrict__ out) {
    int i = blockIdx.x * 256 + threadIdx.x;
    float4 v = in[i];
    out[i] = make_float4(f2tff(v.x), f2tff(v.y), f2tff(v.z), f2tff(v.w));
}

// ---------------------------------------------------------------------------
// tf32 GEMM: C[M,N] = A[M,K] @ B[K,N] + bias. Pre-rounded operands.
// CTA 128x128, K-step 32, 2-stage cp.async, 4 warps x (64x64 warp tile).
// ---------------------------------------------------------------------------
#define AS_STR 36
#define BS_STR 136
#define A_STAGE (128 * AS_STR)
#define B_STAGE (32 * BS_STR)
#define GEMM_SMEM_BYTES ((2 * A_STAGE + 2 * B_STAGE) * 4)

__device__ __forceinline__ void gemm_core(
    const float* __restrict__ A, const float* __restrict__ B,
    const float* __restrict__ bias, float* __restrict__ C,
    int N, int K, int colb, int by, int roundC)
{
    extern __shared__ float sm[];
    float* As = sm;
    float* Bs = sm + 2 * A_STAGE;
    const uint32_t as_u = (uint32_t)__cvta_generic_to_shared(As);
    const uint32_t bs_u = (uint32_t)__cvta_generic_to_shared(Bs);

    const int tid  = threadIdx.x;
    const int lane = tid & 31;
    const int wid  = tid >> 5;          // 0..3
    const int wm = (wid & 1) * 64;
    const int wn = (wid >> 1) * 64;
    const int g  = lane >> 2;
    const int tg = lane & 3;

    float acc[4][8][4];
    #pragma unroll
    for (int mt = 0; mt < 4; mt++)
        #pragma unroll
        for (int nt = 0; nt < 8; nt++)
            #pragma unroll
            for (int i = 0; i < 4; i++) acc[mt][nt][i] = 0.f;

    auto issue = [&](int st, int k0) {
        #pragma unroll
        for (int p = 0; p < 8; p++) {          // A tile 128x32
            int idx = p * 128 + tid;
            int r = idx >> 3, c = (idx & 7) << 2;
            cpa16(as_u + (uint32_t)(st * A_STAGE + r * AS_STR + c) * 4,
                  A + (size_t)(by * 128 + r) * K + k0 + c);
        }
        #pragma unroll
        for (int p = 0; p < 8; p++) {          // B tile 32x128
            int idx = p * 128 + tid;
            int r = idx >> 5, c = (idx & 31) << 2;
            cpa16(bs_u + (uint32_t)(st * B_STAGE + r * BS_STR + c) * 4,
                  B + (size_t)(k0 + r) * N + colb + c);
        }
    };

    const int nsteps = K / 32;
    issue(0, 0);
    cpa_commit();

    for (int s = 0; s < nsteps; s++) {
        if (s + 1 < nsteps) {
            issue((s + 1) & 1, (s + 1) * 32);
            cpa_commit();
            cpa_wait<1>();
        } else {
            cpa_wait<0>();
        }
        __syncthreads();

        const float* Ab = As + (s & 1) * A_STAGE;
        const float* Bb = Bs + (s & 1) * B_STAGE;

        #pragma unroll
        for (int kk = 0; kk < 32; kk += 8) {
            unsigned af[4][4], bf[8][2];
            #pragma unroll
            for (int mt = 0; mt < 4; mt++) {
                const float* sp = &Ab[(wm + mt * 16 + g) * AS_STR + kk + tg];
                af[mt][0] = __float_as_uint(sp[0]);
                af[mt][1] = __float_as_uint(sp[8 * AS_STR]);
                af[mt][2] = __float_as_uint(sp[4]);
                af[mt][3] = __float_as_uint(sp[8 * AS_STR + 4]);
            }
            #pragma unroll
            for (int nt = 0; nt < 8; nt++) {
                const float* sp = &Bb[(kk + tg) * BS_STR + wn + nt * 8 + g];
                bf[nt][0] = __float_as_uint(sp[0]);
                bf[nt][1] = __float_as_uint(sp[4 * BS_STR]);
            }
            #pragma unroll
            for (int mt = 0; mt < 4; mt++)
                #pragma unroll
                for (int nt = 0; nt < 8; nt++)
                    mma8(acc[mt][nt], af[mt], bf[nt]);
        }
        __syncthreads();
    }

    #pragma unroll
    for (int mt = 0; mt < 4; mt++) {
        const int row = by * 128 + wm + mt * 16 + g;
        #pragma unroll
        for (int nt = 0; nt < 8; nt++) {
            const int col = colb + wn + nt * 8 + tg * 2;
            const float b0 = bias[col], b1 = bias[col + 1];
            float v0 = acc[mt][nt][0] + b0, v1 = acc[mt][nt][1] + b1;
            float v2 = acc[mt][nt][2] + b0, v3 = acc[mt][nt][3] + b1;
            if (roundC) {
                v0 = f2tff(v0); v1 = f2tff(v1);
                v2 = f2tff(v2); v3 = f2tff(v3);
            }
            *(float2*)(C + (size_t)row * N + col) = make_float2(v0, v1);
            *(float2*)(C + (size_t)(row + 8) * N + col) = make_float2(v2, v3);
        }
    }
}

// Fused QKV projection: bx 0..15 -> Wq, 16..19 -> Wk, 20..23 -> Wv
__global__ __launch_bounds__(128)
void gemm_qkv(const float* __restrict__ x,
              const float* __restrict__ Wq, const float* __restrict__ bq,
              const float* __restrict__ Wk, const float* __restrict__ bk,
              const float* __restrict__ Wv, const float* __restrict__ bv,
              float* __restrict__ Qo, float* __restrict__ Ko, float* __restrict__ Vo)
{
    const int bx = blockIdx.x;
    const float* B; const float* bias; float* C; int N, colb;
    if (bx < 16)      { B = Wq; bias = bq; C = Qo; N = D_MODEL; colb = bx * 128; }
    else if (bx < 20) { B = Wk; bias = bk; C = Ko; N = KV_DIM;  colb = (bx - 16) * 128; }
    else              { B = Wv; bias = bv; C = Vo; N = KV_DIM;  colb = (bx - 20) * 128; }
    gemm_core(x, B, bias, C, N, D_MODEL, colb, blockIdx.y, 1);
}

__global__ __launch_bounds__(128)
void gemm_o(const float* __restrict__ A, const float* __restrict__ B,
            const float* __restrict__ bias, float* __restrict__ C)
{
    gemm_core(A, B, bias, C, D_MODEL, D_MODEL, blockIdx.x * 128, blockIdx.y, 0);
}

// ---------------------------------------------------------------------------
// Flash attention, tf32 MMA. 8 warps/CTA x 32 query rows = 256-query tiles.
// exp2-domain softmax (log2e folded into Q scale). Pre-rounded Q/K/V.
// ---------------------------------------------------------------------------
#define KS_STR 68
#define VS_STR 72
#define PS_STR 68
#define K_STAGE (64 * KS_STR)
#define V_STAGE (64 * VS_STR)
#define QROWS   256
#define ATTN_SMEM_BYTES ((2 * K_STAGE + 2 * V_STAGE + QROWS * PS_STR) * 4)
#define QSCALE  (0.125f * 1.4426950408889634f)

__global__ __launch_bounds__(256)
void attn_tf32(const float* __restrict__ Q, const float* __restrict__ K,
               const float* __restrict__ V, float* __restrict__ C)
{
    extern __shared__ float sm[];
    float* Ks = sm;                            // [2][64][KS_STR]
    float* Vs = sm + 2 * K_STAGE;              // [2][64][VS_STR]
    float* QP = Vs + 2 * V_STAGE;              // [256][PS_STR]
    const uint32_t ks_u = (uint32_t)__cvta_generic_to_shared(Ks);
    const uint32_t vs_u = (uint32_t)__cvta_generic_to_shared(Vs);

    const int tid  = threadIdx.x;
    const int lane = tid & 31;
    const int wid  = tid >> 5;                 // 0..7
    const int g    = lane >> 2;
    const int tg   = lane & 3;
    const int rA   = wid * 32;
    const int rB   = rA + 16;

    const int qt = blockIdx.x;                 // 256-query tile
    const int h  = blockIdx.y;
    const int b  = blockIdx.z;
    const int hkv = h >> 2;

    auto issueKV = [&](int st, int kt) {
        #pragma unroll
        for (int p = 0; p < 4; p++) {
            int idx = p * 256 + tid;
            int j = idx >> 4, c = (idx & 15) << 2;
            const size_t go = (size_t)(b * SEQ + kt * 64 + j) * KV_DIM + hkv * HDIM + c;
            cpa16(ks_u + (uint32_t)(st * K_STAGE + j * KS_STR + c) * 4, K + go);
            cpa16(vs_u + (uint32_t)(st * V_STAGE + j * VS_STR + c) * 4, V + go);
        }
    };

    issueKV(0, 0);
    cpa_commit();

    // Stage Q scaled by 0.125*log2(e), re-rounded to tf32
    #pragma unroll
    for (int p = 0; p < 16; p++) {
        int idx = p * 256 + tid;
        int r = idx >> 4, c4 = (idx & 15) << 2;
        float4 q4 = *(const float4*)(Q + (size_t)(b * SEQ + qt * QROWS + r) * D_MODEL
                                       + h * HDIM + c4);
        *(float4*)&QP[r * PS_STR + c4] =
            make_float4(f2tff(q4.x * QSCALE), f2tff(q4.y * QSCALE),
                        f2tff(q4.z * QSCALE), f2tff(q4.w * QSCALE));
    }
    __syncthreads();

    unsigned aQ[2][8][4];
    #pragma unroll
    for (int bl = 0; bl < 2; bl++) {
        const int r0 = bl ? rB : rA;
        #pragma unroll
        for (int gk = 0; gk < 8; gk++) {
            const float* sp = &QP[(r0 + g) * PS_STR + gk * 8 + tg];
            aQ[bl][gk][0] = __float_as_uint(sp[0]);
            aQ[bl][gk][1] = __float_as_uint(sp[8 * PS_STR]);
            aQ[bl][gk][2] = __float_as_uint(sp[4]);
            aQ[bl][gk][3] = __float_as_uint(sp[8 * PS_STR + 4]);
        }
    }

    float o[2][8][4];
    #pragma unroll
    for (int bl = 0; bl < 2; bl++)
        #pragma unroll
        for (int nt = 0; nt < 8; nt++)
            #pragma unroll
            for (int i = 0; i < 4; i++) o[bl][nt][i] = 0.f;
    float m[2][2] = {{-1e30f, -1e30f}, {-1e30f, -1e30f}};
    float l[2][2] = {{0.f, 0.f}, {0.f, 0.f}};

    for (int kt = 0; kt < SEQ / 64; kt++) {
        if (kt + 1 < SEQ / 64) {
            issueKV((kt + 1) & 1, kt + 1);
            cpa_commit();
            cpa_wait<1>();
        } else {
            cpa_wait<0>();
        }
        __syncthreads();

        const float* Kb = Ks + (kt & 1) * K_STAGE;
        const float* Vb = Vs + (kt & 1) * V_STAGE;

        // S = Q @ K^T (log2 domain)
        float s[2][8][4];
        #pragma unroll
        for (int bl = 0; bl < 2; bl++)
            #pragma unroll
            for (int nt = 0; nt < 8; nt++)
                #pragma unroll
                for (int i = 0; i < 4; i++) s[bl][nt][i] = 0.f;

        #pragma unroll
        for (int gk = 0; gk < 8; gk++) {
            #pragma unroll
            for (int nt = 0; nt < 8; nt++) {
                unsigned bk[2];
                const float* kb = &Kb[(nt * 8 + g) * KS_STR + gk * 8 + tg];
                bk[0] = __float_as_uint(kb[0]);
                bk[1] = __float_as_uint(kb[4]);
                mma8(s[0][nt], aQ[0][gk], bk);
                mma8(s[1][nt], aQ[1][gk], bk);
            }
        }

        // Online softmax (exp2 domain)
        #pragma unroll
        for (int bl = 0; bl < 2; bl++) {
            const int r0 = bl ? rB : rA;
            float tm0 = -1e30f, tm1 = -1e30f;
            #pragma unroll
            for (int nt = 0; nt < 8; nt++) {
                tm0 = fmaxf(tm0, fmaxf(s[bl][nt][0], s[bl][nt][1]));
                tm1 = fmaxf(tm1, fmaxf(s[bl][nt][2], s[bl][nt][3]));
            }
            tm0 = fmaxf(tm0, __shfl_xor_sync(0xffffffffu, tm0, 1));
            tm0 = fmaxf(tm0, __shfl_xor_sync(0xffffffffu, tm0, 2));
            tm1 = fmaxf(tm1, __shfl_xor_sync(0xffffffffu, tm1, 1));
            tm1 = fmaxf(tm1, __shfl_xor_sync(0xffffffffu, tm1, 2));

            float nm0 = fmaxf(m[bl][0], tm0), nm1 = fmaxf(m[bl][1], tm1);
            float c0 = ex2(m[bl][0] - nm0), c1 = ex2(m[bl][1] - nm1);
            m[bl][0] = nm0; m[bl][1] = nm1;

            float rs0 = 0.f, rs1 = 0.f;
            #pragma unroll
            for (int nt = 0; nt < 8; nt++) {
                float p0 = ex2(s[bl][nt][0] - nm0);
                float p1 = ex2(s[bl][nt][1] - nm0);
                float p2 = ex2(s[bl][nt][2] - nm1);
                float p3 = ex2(s[bl][nt][3] - nm1);
                rs0 += p0 + p1;
                rs1 += p2 + p3;
                *(float2*)&QP[(r0 + g) * PS_STR + nt * 8 + tg * 2] =
                    make_float2(f2tff(p0), f2tff(p1));
                *(float2*)&QP[(r0 + g + 8) * PS_STR + nt * 8 + tg * 2] =
                    make_float2(f2tff(p2), f2tff(p3));
                o[bl][nt][0] *= c0; o[bl][nt][1] *= c0;
                o[bl][nt][2] *= c1; o[bl][nt][3] *= c1;
            }
            rs0 += __shfl_xor_sync(0xffffffffu, rs0, 1);
            rs0 += __shfl_xor_sync(0xffffffffu, rs0, 2);
            rs1 += __shfl_xor_sync(0xffffffffu, rs1, 1);
            rs1 += __shfl_xor_sync(0xffffffffu, rs1, 2);
            l[bl][0] = l[bl][0] * c0 + rs0;
            l[bl][1] = l[bl][1] * c1 + rs1;
        }
        __syncwarp();

        // O += P @ V
        #pragma unroll
        for (int gk = 0; gk < 8; gk++) {
            unsigned aP0[4], aP1[4];
            const float* p0 = &QP[(rA + g) * PS_STR + gk * 8 + tg];
            aP0[0] = __float_as_uint(p0[0]);
            aP0[1] = __float_as_uint(p0[8 * PS_STR]);
            aP0[2] = __float_as_uint(p0[4]);
            aP0[3] = __float_as_uint(p0[8 * PS_STR + 4]);
            const float* p1 = &QP[(rB + g) * PS_STR + gk * 8 + tg];
            aP1[0] = __float_as_uint(p1[0]);
            aP1[1] = __float_as_uint(p1[8 * PS_STR]);
            aP1[2] = __float_as_uint(p1[4]);
            aP1[3] = __float_as_uint(p1[8 * PS_STR + 4]);
            #pragma unroll
            for (int nt = 0; nt < 8; nt++) {
                unsigned bv[2];
                const float* vb = &Vb[(gk * 8 + tg) * VS_STR + nt * 8 + g];
                bv[0] = __float_as_uint(vb[0]);
                bv[1] = __float_as_uint(vb[4 * VS_STR]);
                mma8(o[0][nt], aP0, bv);
                mma8(o[1][nt], aP1, bv);
            }
        }
        __syncthreads();
    }

    // Normalize and write context (tf32-rounded for the O projection)
    #pragma unroll
    for (int bl = 0; bl < 2; bl++) {
        const int r0 = bl ? rB : rA;
        const float i0 = 1.f / l[bl][0], i1 = 1.f / l[bl][1];
        #pragma unroll
        for (int nt = 0; nt < 8; nt++) {
            const size_t row = (size_t)(b * SEQ + qt * QROWS + r0 + g);
            const int col = h * HDIM + nt * 8 + tg * 2;
            *(float2*)(C + row * D_MODEL + col) =
                make_float2(f2tff(o[bl][nt][0] * i0), f2tff(o[bl][nt][1] * i0));
            *(float2*)(C + (row + 8) * D_MODEL + col) =
                make_float2(f2tff(o[bl][nt][2] * i1), f2tff(o[bl][nt][3] * i1));
        }
    }
}

// ---------------------------------------------------------------------------
// Launch
// ---------------------------------------------------------------------------
extern "C" void kernel_launch(void* const* d_in, const int* in_sizes, int n_in,
                              void* d_out, int out_size)
{
    const float* x  = (const float*)d_in[0];
    const float* Wq = (const float*)d_in[1];
    const float* bq = (const float*)d_in[2];
    const float* Wk = (const float*)d_in[3];
    const float* bk = (const float*)d_in[4];
    const float* Wv = (const float*)d_in[5];
    const float* bv = (const float*)d_in[6];
    const float* Wo = (const float*)d_in[7];
    const float* bo = (const float*)d_in[8];
    float* out = (float*)d_out;

    float *pX, *pWq, *pWk, *pWv, *pWo, *pQ, *pK, *pV, *pC;
    cudaGetSymbolAddress((void**)&pX, g_X);
    cudaGetSymbolAddress((void**)&pWq, g_Wq);
    cudaGetSymbolAddress((void**)&pWk, g_Wk);
    cudaGetSymbolAddress((void**)&pWv, g_Wv);
    cudaGetSymbolAddress((void**)&pWo, g_Wo);
    cudaGetSymbolAddress((void**)&pQ, g_Q);
    cudaGetSymbolAddress((void**)&pK, g_K);
    cudaGetSymbolAddress((void**)&pV, g_V);
    cudaGetSymbolAddress((void**)&pC, g_C);

    cudaFuncSetAttribute(gemm_qkv, cudaFuncAttributeMaxDynamicSharedMemorySize, GEMM_SMEM_BYTES);
    cudaFuncSetAttribute(gemm_o,   cudaFuncAttributeMaxDynamicSharedMemorySize, GEMM_SMEM_BYTES);
    cudaFuncSetAttribute(attn_tf32, cudaFuncAttributeMaxDynamicSharedMemorySize, ATTN_SMEM_BYTES);

    // Pre-pass: tf32-RNA rounding of activations + weights
    cvt_tf32_kernel<<<(MTOK * D_MODEL / 4) / 256, 256>>>((const float4*)x,  (float4*)pX);
    cvt_tf32_kernel<<<(D_MODEL * D_MODEL / 4) / 256, 256>>>((const float4*)Wq, (float4*)pWq);
    cvt_tf32_kernel<<<(D_MODEL * KV_DIM  / 4) / 256, 256>>>((const float4*)Wk, (float4*)pWk);
    cvt_tf32_kernel<<<(D_MODEL * KV_DIM  / 4) / 256, 256>>>((const float4*)Wv, (float4*)pWv);
    cvt_tf32_kernel<<<(D_MODEL * D_MODEL / 4) / 256, 256>>>((const float4*)Wo, (float4*)pWo);

    // Fused QKV projection (outputs tf32-rounded)
    gemm_qkv<<<dim3(24, MTOK / 128), 128, GEMM_SMEM_BYTES>>>(
        pX, pWq, bq, pWk, bk, pWv, bv, pQ, pK, pV);

    // Attention (256-query tiles, 8 warps)
    attn_tf32<<<dim3(SEQ / QROWS, HEADS, BATCH), 256, ATTN_SMEM_BYTES>>>(pQ, pK, pV, pC);

    // Output projection
    gemm_o<<<dim3(D_MODEL / 128, MTOK / 128), 128, GEMM_SMEM_BYTES>>>(pC, pWo, bo, out);
}

// round 8
// speedup vs baseline: 7.8091x; 1.8699x over previous
#include <cuda_runtime.h>
#include <cuda_fp16.h>
#include <cstdint>

#define D_MODEL 2048
#define KV_DIM  512
#define BATCH   2
#define SEQ     2048
#define MTOK    4096
#define HEADS   32
#define HDIM    64

// Scratch (device globals: no allocations allowed) — fp16 data path
__device__ __half g_X [(size_t)MTOK * D_MODEL];
__device__ __half g_Wq[(size_t)D_MODEL * D_MODEL];
__device__ __half g_Wk[(size_t)D_MODEL * KV_DIM];
__device__ __half g_Wv[(size_t)D_MODEL * KV_DIM];
__device__ __half g_Wo[(size_t)D_MODEL * D_MODEL];
__device__ __half g_Q [(size_t)MTOK * D_MODEL];
__device__ __half g_K [(size_t)MTOK * KV_DIM];
__device__ __half g_V [(size_t)MTOK * KV_DIM];
__device__ __half g_C [(size_t)MTOK * D_MODEL];

// ---------------------------------------------------------------------------
// helpers
// ---------------------------------------------------------------------------
__device__ __forceinline__ float ex2(float x) {
    float r;
    asm("ex2.approx.f32 %0, %1;" : "=f"(r) : "f"(x));
    return r;
}
__device__ __forceinline__ unsigned packh2(float a, float b) {
    __half2 h = __floats2half2_rn(a, b);
    return *reinterpret_cast<unsigned*>(&h);
}
__device__ __forceinline__ void mma16(float* d, const unsigned* a, const unsigned* b) {
    asm volatile(
        "mma.sync.aligned.m16n8k16.row.col.f32.f16.f16.f32 "
        "{%0,%1,%2,%3},{%4,%5,%6,%7},{%8,%9},{%0,%1,%2,%3};"
        : "+f"(d[0]), "+f"(d[1]), "+f"(d[2]), "+f"(d[3])
        : "r"(a[0]), "r"(a[1]), "r"(a[2]), "r"(a[3]), "r"(b[0]), "r"(b[1]));
}
__device__ __forceinline__ void ldsm4(unsigned* r, uint32_t a) {
    asm volatile("ldmatrix.sync.aligned.m8n8.x4.shared.b16 {%0,%1,%2,%3}, [%4];"
                 : "=r"(r[0]), "=r"(r[1]), "=r"(r[2]), "=r"(r[3]) : "r"(a));
}
__device__ __forceinline__ void ldsm4t(unsigned* r, uint32_t a) {
    asm volatile("ldmatrix.sync.aligned.m8n8.x4.trans.shared.b16 {%0,%1,%2,%3}, [%4];"
                 : "=r"(r[0]), "=r"(r[1]), "=r"(r[2]), "=r"(r[3]) : "r"(a));
}
__device__ __forceinline__ void cpa16(uint32_t dst, const void* src) {
    asm volatile("cp.async.cg.shared.global [%0], [%1], 16;" :: "r"(dst), "l"(src));
}
__device__ __forceinline__ void cpa_commit() {
    asm volatile("cp.async.commit_group;");
}
template <int N>
__device__ __forceinline__ void cpa_wait() {
    asm volatile("cp.async.wait_group %0;" :: "n"(N));
}

// ---------------------------------------------------------------------------
// Pre-pass: fp32 -> fp16 (RN)
// ---------------------------------------------------------------------------
__global__ __launch_bounds__(256)
void cvt_f16(const float4* __restrict__ in, uint2* __restrict__ out) {
    int i = blockIdx.x * 256 + threadIdx.x;
    float4 v = in[i];
    uint2 u;
    u.x = packh2(v.x, v.y);
    u.y = packh2(v.z, v.w);
    out[i] = u;
}

// ---------------------------------------------------------------------------
// fp16 GEMM (fp32 accum): C[M,N] = A[M,K] @ B[K,N] + bias.
// CTA 128x128, K-step 32, 3-stage cp.async ring, 4 warps x (64x64).
// A smem [128 rows][80B], B smem [32 k-rows][272B]; LDSM strides give
// conflict-free phases (stride/4 mod 32 = {20,4}-spread).
// ---------------------------------------------------------------------------
#define A_STR 80
#define B_STR 272
#define A_ST  (128 * A_STR)   // 10240 B
#define B_ST  (32 * B_STR)    //  8704 B
#define GEMM_SMEM (3 * (A_ST + B_ST))

__device__ __forceinline__ void gemm_core(
    const __half* __restrict__ A, const __half* __restrict__ B,
    const float* __restrict__ bias, float* __restrict__ Cf, __half* __restrict__ Ch,
    int N, int K, int colb, int by)
{
    extern __shared__ char smg[];
    const uint32_t su = (uint32_t)__cvta_generic_to_shared(smg);

    const int tid  = threadIdx.x;
    const int lane = tid & 31;
    const int wid  = tid >> 5;
    const int wm = (wid & 1) * 64;
    const int wn = (wid >> 1) * 64;
    const int g  = lane >> 2;
    const int tg = lane & 3;

    // ldmatrix lane-address components (constant per thread)
    const int lrow8 = (lane & 7) + ((lane >> 3) & 1) * 8;  // row/k within 16
    const int lhi   = lane >> 4;                           // chunk select

    float acc[4][8][4];
    #pragma unroll
    for (int mt = 0; mt < 4; mt++)
        #pragma unroll
        for (int nt = 0; nt < 8; nt++)
            #pragma unroll
            for (int i = 0; i < 4; i++) acc[mt][nt][i] = 0.f;

    auto issue = [&](int stg) {
        const int st = stg % 3;
        const int k0 = stg * 32;
        const uint32_t ab = su + st * (A_ST + B_ST);
        const uint32_t bb = ab + A_ST;
        #pragma unroll
        for (int p = 0; p < 4; p++) {          // A 128x32 fp16 (512 x 16B)
            int idx = p * 128 + tid;
            int r = idx >> 2, c = idx & 3;
            cpa16(ab + r * A_STR + c * 16, A + (size_t)(by * 128 + r) * K + k0 + c * 8);
        }
        #pragma unroll
        for (int p = 0; p < 4; p++) {          // B 32x128 fp16 (512 x 16B)
            int idx = p * 128 + tid;
            int r = idx >> 4, c = idx & 15;
            cpa16(bb + r * B_STR + c * 16, B + (size_t)(k0 + r) * N + colb + c * 8);
        }
        cpa_commit();
    };

    const int nsteps = K / 32;
    issue(0); issue(1);

    for (int s = 0; s < nsteps; s++) {
        if (s + 2 < nsteps) { issue(s + 2); cpa_wait<2>(); }
        else if (s + 1 < nsteps) cpa_wait<1>();
        else cpa_wait<0>();
        __syncthreads();

        const uint32_t ab = su + (s % 3) * (A_ST + B_ST);
        const uint32_t bb = ab + A_ST;

        #pragma unroll
        for (int kk = 0; kk < 32; kk += 16) {
            unsigned af[4][4], bf[4][4];
            #pragma unroll
            for (int mt = 0; mt < 4; mt++)
                ldsm4(af[mt], ab + (wm + mt * 16 + lrow8) * A_STR
                                 + ((kk >> 3) + lhi) * 16);
            #pragma unroll
            for (int ntp = 0; ntp < 4; ntp++)
                ldsm4t(bf[ntp], bb + (kk + lrow8) * B_STR
                                   + (((wn + ntp * 16) >> 3) + lhi) * 16);
            #pragma unroll
            for (int mt = 0; mt < 4; mt++)
                #pragma unroll
                for (int ntp = 0; ntp < 4; ntp++) {
                    mma16(acc[mt][2 * ntp],     af[mt], bf[ntp] + 0);
                    mma16(acc[mt][2 * ntp + 1], af[mt], bf[ntp] + 2);
                }
        }
        __syncthreads();
    }

    #pragma unroll
    for (int mt = 0; mt < 4; mt++) {
        const int row = by * 128 + wm + mt * 16 + g;
        #pragma unroll
        for (int nt = 0; nt < 8; nt++) {
            const int col = colb + wn + nt * 8 + tg * 2;
            const float b0 = bias[col], b1 = bias[col + 1];
            float v0 = acc[mt][nt][0] + b0, v1 = acc[mt][nt][1] + b1;
            float v2 = acc[mt][nt][2] + b0, v3 = acc[mt][nt][3] + b1;
            if (Ch) {
                *(unsigned*)(Ch + (size_t)row * N + col)       = packh2(v0, v1);
                *(unsigned*)(Ch + (size_t)(row + 8) * N + col) = packh2(v2, v3);
            } else {
                *(float2*)(Cf + (size_t)row * N + col)       = make_float2(v0, v1);
                *(float2*)(Cf + (size_t)(row + 8) * N + col) = make_float2(v2, v3);
            }
        }
    }
}

// Fused QKV projection: bx 0..15 -> Wq, 16..19 -> Wk, 20..23 -> Wv
__global__ __launch_bounds__(128)
void gemm_qkv(const __half* __restrict__ x,
              const __half* __restrict__ Wq, const float* __restrict__ bq,
              const __half* __restrict__ Wk, const float* __restrict__ bk,
              const __half* __restrict__ Wv, const float* __restrict__ bv,
              __half* __restrict__ Qo, __half* __restrict__ Ko, __half* __restrict__ Vo)
{
    const int bx = blockIdx.x;
    const __half* B; const float* bias; __half* C; int N, colb;
    if (bx < 16)      { B = Wq; bias = bq; C = Qo; N = D_MODEL; colb = bx * 128; }
    else if (bx < 20) { B = Wk; bias = bk; C = Ko; N = KV_DIM;  colb = (bx - 16) * 128; }
    else              { B = Wv; bias = bv; C = Vo; N = KV_DIM;  colb = (bx - 20) * 128; }
    gemm_core(x, B, bias, nullptr, C, N, D_MODEL, colb, blockIdx.y);
}

__global__ __launch_bounds__(128)
void gemm_o(const __half* __restrict__ A, const __half* __restrict__ B,
            const float* __restrict__ bias, float* __restrict__ C)
{
    gemm_core(A, B, bias, C, nullptr, D_MODEL, D_MODEL, blockIdx.x * 128, blockIdx.y);
}

// ---------------------------------------------------------------------------
// Flash attention, fp16 MMA (fp32 accum/softmax). 8 warps x 32 q-rows = 256/CTA.
// K: plain LDSM ([key][d] is the B-operand layout). V: LDSM.trans.
// P stays in registers (S-accum fragment == PV A-fragment).
// ---------------------------------------------------------------------------
#define KV_STR 144
#define K_ST   (64 * KV_STR)          // 9216 B per stage
#define QROWS  256
#define ATTN_SMEM (4 * K_ST + QROWS * KV_STR)   // K[2] V[2] + Qs = 73728 B
#define QSCALE (0.125f * 1.4426950408889634f)

__global__ __launch_bounds__(256)
void attn_f16(const __half* __restrict__ Q, const __half* __restrict__ K,
              const __half* __restrict__ V, __half* __restrict__ C)
{
    extern __shared__ char sma[];
    const uint32_t su = (uint32_t)__cvta_generic_to_shared(sma);
    const uint32_t qOff = su + 4 * K_ST;

    const int tid  = threadIdx.x;
    const int lane = tid & 31;
    const int wid  = tid >> 5;
    const int g    = lane >> 2;
    const int tg   = lane & 3;
    const int rA   = wid * 32;
    const int lrow8 = (lane & 7) + ((lane >> 3) & 1) * 8;
    const int lhi   = lane >> 4;

    const int qt = blockIdx.x;
    const int h  = blockIdx.y;
    const int b  = blockIdx.z;
    const int hkv = h >> 2;

    auto issueKV = [&](int st, int kt) {
        #pragma unroll
        for (int p = 0; p < 4; p++) {          // 512 K-chunks + 512 V-chunks
            int idx = p * 256 + tid;
            int sel = idx >> 9;
            int jj = (idx >> 3) & 63;
            int c  = idx & 7;
            const __half* src = (sel ? V : K)
                + (size_t)(b * SEQ + kt * 64 + jj) * KV_DIM + hkv * HDIM + c * 8;
            cpa16(su + (sel ? 2 : 0) * K_ST + st * K_ST + jj * KV_STR + c * 16, src);
        }
        cpa_commit();
    };

    issueKV(0, 0);

    // Stage Q: fp16 -> fp32 scale (exact fp32 QSCALE) -> fp16 -> smem
    #pragma unroll
    for (int p = 0; p < 32; p++) {
        int idx = p * 256 + tid;               // 8192 half2
        int r = idx >> 5, c2 = idx & 31;
        __half2 q2 = *(const __half2*)(Q + (size_t)(b * SEQ + qt * QROWS + r) * D_MODEL
                                         + h * HDIM + c2 * 2);
        float2 qf = __half22float2(q2);
        *(unsigned*)(sma + 4 * K_ST + r * KV_STR + c2 * 4) =
            packh2(qf.x * QSCALE, qf.y * QSCALE);
    }
    __syncthreads();

    // Q fragments: 2 row-blocks x 4 k16-steps
    unsigned aQ[2][4][4];
    #pragma unroll
    for (int bl = 0; bl < 2; bl++)
        #pragma unroll
        for (int kki = 0; kki < 4; kki++)
            ldsm4(aQ[bl][kki], qOff + (rA + bl * 16 + lrow8) * KV_STR
                                    + (kki * 2 + lhi) * 16);

    float o[2][8][4];
    #pragma unroll
    for (int bl = 0; bl < 2; bl++)
        #pragma unroll
        for (int nt = 0; nt < 8; nt++)
            #pragma unroll
            for (int i = 0; i < 4; i++) o[bl][nt][i] = 0.f;
    float m[2][2] = {{-1e30f, -1e30f}, {-1e30f, -1e30f}};
    float l[2][2] = {{0.f, 0.f}, {0.f, 0.f}};

    for (int kt = 0; kt < SEQ / 64; kt++) {
        if (kt + 1 < SEQ / 64) { issueKV((kt + 1) & 1, kt + 1); cpa_wait<1>(); }
        else cpa_wait<0>();
        __syncthreads();

        const uint32_t kb = su + (kt & 1) * K_ST;
        const uint32_t vb = su + 2 * K_ST + (kt & 1) * K_ST;

        // S = Q @ K^T (log2-scaled)
        float s[2][8][4];
        #pragma unroll
        for (int bl = 0; bl < 2; bl++)
            #pragma unroll
            for (int nt = 0; nt < 8; nt++)
                #pragma unroll
                for (int i = 0; i < 4; i++) s[bl][nt][i] = 0.f;

        #pragma unroll
        for (int kki = 0; kki < 4; kki++) {
            #pragma unroll
            for (int ntp = 0; ntp < 4; ntp++) {
                unsigned bK[4];
                // keys ntp*16 + (lane&7) + 8*(lane>>4); kchunk 2*kki + ((lane>>3)&1)
                ldsm4(bK, kb + (ntp * 16 + (lane & 7) + lhi * 8) * KV_STR
                             + (kki * 2 + ((lane >> 3) & 1)) * 16);
                mma16(s[0][2 * ntp],     aQ[0][kki], bK + 0);
                mma16(s[0][2 * ntp + 1], aQ[0][kki], bK + 2);
                mma16(s[1][2 * ntp],     aQ[1][kki], bK + 0);
                mma16(s[1][2 * ntp + 1], aQ[1][kki], bK + 2);
            }
        }

        // Online softmax (exp2 domain); s overwritten with P (fp32)
        #pragma unroll
        for (int bl = 0; bl < 2; bl++) {
            float tm0 = -1e30f, tm1 = -1e30f;
            #pragma unroll
            for (int nt = 0; nt < 8; nt++) {
                tm0 = fmaxf(tm0, fmaxf(s[bl][nt][0], s[bl][nt][1]));
                tm1 = fmaxf(tm1, fmaxf(s[bl][nt][2], s[bl][nt][3]));
            }
            tm0 = fmaxf(tm0, __shfl_xor_sync(0xffffffffu, tm0, 1));
            tm0 = fmaxf(tm0, __shfl_xor_sync(0xffffffffu, tm0, 2));
            tm1 = fmaxf(tm1, __shfl_xor_sync(0xffffffffu, tm1, 1));
            tm1 = fmaxf(tm1, __shfl_xor_sync(0xffffffffu, tm1, 2));

            float nm0 = fmaxf(m[bl][0], tm0), nm1 = fmaxf(m[bl][1], tm1);
            float c0 = ex2(m[bl][0] - nm0), c1 = ex2(m[bl][1] - nm1);
            m[bl][0] = nm0; m[bl][1] = nm1;

            float rs0 = 0.f, rs1 = 0.f;
            #pragma unroll
            for (int nt = 0; nt < 8; nt++) {
                float p0 = ex2(s[bl][nt][0] - nm0);
                float p1 = ex2(s[bl][nt][1] - nm0);
                float p2 = ex2(s[bl][nt][2] - nm1);
                float p3 = ex2(s[bl][nt][3] - nm1);
                s[bl][nt][0] = p0; s[bl][nt][1] = p1;
                s[bl][nt][2] = p2; s[bl][nt][3] = p3;
                rs0 += p0 + p1;
                rs1 += p2 + p3;
                o[bl][nt][0] *= c0; o[bl][nt][1] *= c0;
                o[bl][nt][2] *= c1; o[bl][nt][3] *= c1;
            }
            rs0 += __shfl_xor_sync(0xffffffffu, rs0, 1);
            rs0 += __shfl_xor_sync(0xffffffffu, rs0, 2);
            rs1 += __shfl_xor_sync(0xffffffffu, rs1, 1);
            rs1 += __shfl_xor_sync(0xffffffffu, rs1, 2);
            l[bl][0] = l[bl][0] * c0 + rs0;
            l[bl][1] = l[bl][1] * c1 + rs1;
        }

        // O += P @ V ; P packed straight from registers
        #pragma unroll
        for (int j = 0; j < 4; j++) {
            unsigned aP0[4], aP1[4];
            aP0[0] = packh2(s[0][2 * j][0], s[0][2 * j][1]);
            aP0[1] = packh2(s[0][2 * j][2], s[0][2 * j][3]);
            aP0[2] = packh2(s[0][2 * j + 1][0], s[0][2 * j + 1][1]);
            aP0[3] = packh2(s[0][2 * j + 1][2], s[0][2 * j + 1][3]);
            aP1[0] = packh2(s[1][2 * j][0], s[1][2 * j][1]);
            aP1[1] = packh2(s[1][2 * j][2], s[1][2 * j][3]);
            aP1[2] = packh2(s[1][2 * j + 1][0], s[1][2 * j + 1][1]);
            aP1[3] = packh2(s[1][2 * j + 1][2], s[1][2 * j + 1][3]);
            #pragma unroll
            for (int ntp = 0; ntp < 4; ntp++) {
                unsigned bV[4];
                // keys j*16 + lrow8 ; d-chunk ntp*2 + lhi (transposed load)
                ldsm4t(bV, vb + (j * 16 + lrow8) * KV_STR + (ntp * 2 + lhi) * 16);
                mma16(o[0][2 * ntp],     aP0, bV + 0);
                mma16(o[0][2 * ntp + 1], aP0, bV + 2);
                mma16(o[1][2 * ntp],     aP1, bV + 0);
                mma16(o[1][2 * ntp + 1], aP1, bV + 2);
            }
        }
        __syncthreads();   // stage consumed before next issue overwrites
    }

    // Normalize, write context fp16
    #pragma unroll
    for (int bl = 0; bl < 2; bl++) {
        const float i0 = 1.f / l[bl][0], i1 = 1.f / l[bl][1];
        #pragma unroll
        for (int nt = 0; nt < 8; nt++) {
            const size_t row = (size_t)(b * SEQ + qt * QROWS + rA + bl * 16 + g);
            const int col = h * HDIM + nt * 8 + tg * 2;
            *(unsigned*)(C + row * D_MODEL + col) =
                packh2(o[bl][nt][0] * i0, o[bl][nt][1] * i0);
            *(unsigned*)(C + (row + 8) * D_MODEL + col) =
                packh2(o[bl][nt][2] * i1, o[bl][nt][3] * i1);
        }
    }
}

// ---------------------------------------------------------------------------
// Launch
// ---------------------------------------------------------------------------
extern "C" void kernel_launch(void* const* d_in, const int* in_sizes, int n_in,
                              void* d_out, int out_size)
{
    const float* x  = (const float*)d_in[0];
    const float* Wq = (const float*)d_in[1];
    const float* bq = (const float*)d_in[2];
    const float* Wk = (const float*)d_in[3];
    const float* bk = (const float*)d_in[4];
    const float* Wv = (const float*)d_in[5];
    const float* bv = (const float*)d_in[6];
    const float* Wo = (const float*)d_in[7];
    const float* bo = (const float*)d_in[8];
    float* out = (float*)d_out;

    __half *pX, *pWq, *pWk, *pWv, *pWo, *pQ, *pK, *pV, *pC;
    cudaGetSymbolAddress((void**)&pX, g_X);
    cudaGetSymbolAddress((void**)&pWq, g_Wq);
    cudaGetSymbolAddress((void**)&pWk, g_Wk);
    cudaGetSymbolAddress((void**)&pWv, g_Wv);
    cudaGetSymbolAddress((void**)&pWo, g_Wo);
    cudaGetSymbolAddress((void**)&pQ, g_Q);
    cudaGetSymbolAddress((void**)&pK, g_K);
    cudaGetSymbolAddress((void**)&pV, g_V);
    cudaGetSymbolAddress((void**)&pC, g_C);

    cudaFuncSetAttribute(gemm_qkv, cudaFuncAttributeMaxDynamicSharedMemorySize, GEMM_SMEM);
    cudaFuncSetAttribute(gemm_o,   cudaFuncAttributeMaxDynamicSharedMemorySize, GEMM_SMEM);
    cudaFuncSetAttribute(attn_f16, cudaFuncAttributeMaxDynamicSharedMemorySize, ATTN_SMEM);

    // Pre-pass: fp32 -> fp16
    cvt_f16<<<(MTOK * D_MODEL / 4) / 256, 256>>>((const float4*)x,  (uint2*)pX);
    cvt_f16<<<(D_MODEL * D_MODEL / 4) / 256, 256>>>((const float4*)Wq, (uint2*)pWq);
    cvt_f16<<<(D_MODEL * KV_DIM  / 4) / 256, 256>>>((const float4*)Wk, (uint2*)pWk);
    cvt_f16<<<(D_MODEL * KV_DIM  / 4) / 256, 256>>>((const float4*)Wv, (uint2*)pWv);
    cvt_f16<<<(D_MODEL * D_MODEL / 4) / 256, 256>>>((const float4*)Wo, (uint2*)pWo);

    // Fused QKV projection (fp16 outputs)
    gemm_qkv<<<dim3(24, MTOK / 128), 128, GEMM_SMEM>>>(
        pX, pWq, bq, pWk, bk, pWv, bv, pQ, pK, pV);

    // Attention
    attn_f16<<<dim3(SEQ / QROWS, HEADS, BATCH), 256, ATTN_SMEM>>>(pQ, pK, pV, pC);

    // Output projection (fp32 output)
    gemm_o<<<dim3(D_MODEL / 128, MTOK / 128), 128, GEMM_SMEM>>>(pC, pWo, bo, out);
}

// round 9
// speedup vs baseline: 8.1145x; 1.0391x over previous
#include <cuda_runtime.h>
#include <cuda_fp16.h>
#include <cstdint>

#define D_MODEL 2048
#define KV_DIM  512
#define BATCH   2
#define SEQ     2048
#define MTOK    4096
#define HEADS   32
#define HDIM    64

// Scratch (device globals: no allocations allowed) — fp16 data path
__device__ __half g_X [(size_t)MTOK * D_MODEL];
__device__ __half g_Wq[(size_t)D_MODEL * D_MODEL];
__device__ __half g_Wk[(size_t)D_MODEL * KV_DIM];
__device__ __half g_Wv[(size_t)D_MODEL * KV_DIM];
__device__ __half g_Wo[(size_t)D_MODEL * D_MODEL];
__device__ __half g_Q [(size_t)MTOK * D_MODEL];
__device__ __half g_K [(size_t)MTOK * KV_DIM];
__device__ __half g_V [(size_t)MTOK * KV_DIM];
__device__ __half g_C [(size_t)MTOK * D_MODEL];

// ---------------------------------------------------------------------------
// helpers
// ---------------------------------------------------------------------------
__device__ __forceinline__ float ex2(float x) {
    float r;
    asm("ex2.approx.f32 %0, %1;" : "=f"(r) : "f"(x));
    return r;
}
__device__ __forceinline__ unsigned ex2h2(unsigned x) {
    unsigned r;
    asm("ex2.approx.f16x2 %0, %1;" : "=r"(r) : "r"(x));
    return r;
}
__device__ __forceinline__ unsigned packh2(float a, float b) {
    __half2 h = __floats2half2_rn(a, b);
    return *reinterpret_cast<unsigned*>(&h);
}
__device__ __forceinline__ float2 unpackh2(unsigned u) {
    return __half22float2(*reinterpret_cast<__half2*>(&u));
}
__device__ __forceinline__ void mma16(float* d, const unsigned* a, const unsigned* b) {
    asm volatile(
        "mma.sync.aligned.m16n8k16.row.col.f32.f16.f16.f32 "
        "{%0,%1,%2,%3},{%4,%5,%6,%7},{%8,%9},{%0,%1,%2,%3};"
        : "+f"(d[0]), "+f"(d[1]), "+f"(d[2]), "+f"(d[3])
        : "r"(a[0]), "r"(a[1]), "r"(a[2]), "r"(a[3]), "r"(b[0]), "r"(b[1]));
}
__device__ __forceinline__ void ldsm4(unsigned* r, uint32_t a) {
    asm volatile("ldmatrix.sync.aligned.m8n8.x4.shared.b16 {%0,%1,%2,%3}, [%4];"
                 : "=r"(r[0]), "=r"(r[1]), "=r"(r[2]), "=r"(r[3]) : "r"(a));
}
__device__ __forceinline__ void ldsm4t(unsigned* r, uint32_t a) {
    asm volatile("ldmatrix.sync.aligned.m8n8.x4.trans.shared.b16 {%0,%1,%2,%3}, [%4];"
                 : "=r"(r[0]), "=r"(r[1]), "=r"(r[2]), "=r"(r[3]) : "r"(a));
}
__device__ __forceinline__ void cpa16(uint32_t dst, const void* src) {
    asm volatile("cp.async.cg.shared.global [%0], [%1], 16;" :: "r"(dst), "l"(src));
}
__device__ __forceinline__ void cpa_commit() {
    asm volatile("cp.async.commit_group;");
}
template <int N>
__device__ __forceinline__ void cpa_wait() {
    asm volatile("cp.async.wait_group %0;" :: "n"(N));
}

// ---------------------------------------------------------------------------
// Fused pre-pass: fp32 -> fp16 for x + all 4 weights in one launch.
// Segments (float4 units): x 2M | Wq 1M | Wk 256K | Wv 256K | Wo 1M
// ---------------------------------------------------------------------------
#define SEG0 (MTOK * D_MODEL / 4)
#define SEG1 (SEG0 + D_MODEL * D_MODEL / 4)
#define SEG2 (SEG1 + D_MODEL * KV_DIM / 4)
#define SEG3 (SEG2 + D_MODEL * KV_DIM / 4)
#define SEG4 (SEG3 + D_MODEL * D_MODEL / 4)

__global__ __launch_bounds__(256)
void cvt_all(const float4* __restrict__ x,  const float4* __restrict__ wq,
             const float4* __restrict__ wk, const float4* __restrict__ wv,
             const float4* __restrict__ wo,
             uint2* __restrict__ ox,  uint2* __restrict__ owq,
             uint2* __restrict__ owk, uint2* __restrict__ owv,
             uint2* __restrict__ owo)
{
    int i = blockIdx.x * 256 + threadIdx.x;
    const float4* src; uint2* dst; int off;
    if (i < SEG0)      { src = x;  dst = ox;  off = i; }
    else if (i < SEG1) { src = wq; dst = owq; off = i - SEG0; }
    else if (i < SEG2) { src = wk; dst = owk; off = i - SEG1; }
    else if (i < SEG3) { src = wv; dst = owv; off = i - SEG2; }
    else               { src = wo; dst = owo; off = i - SEG3; }
    float4 v = src[off];
    uint2 u;
    u.x = packh2(v.x, v.y);
    u.y = packh2(v.z, v.w);
    dst[off] = u;
}

// ---------------------------------------------------------------------------
// fp16 GEMM (fp32 accum): C[M,N] = A[M,K] @ B[K,N] + bias.
// CTA 128x128, K-step 32, 3-stage ring, ONE barrier per stage,
// 4 warps x (64x64), LDSM operand loads.
// ---------------------------------------------------------------------------
#define A_STR 80
#define B_STR 272
#define A_ST  (128 * A_STR)
#define B_ST  (32 * B_STR)
#define GEMM_SMEM (3 * (A_ST + B_ST))

__device__ __forceinline__ void gemm_core(
    const __half* __restrict__ A, const __half* __restrict__ B,
    const float* __restrict__ bias, float* __restrict__ Cf, __half* __restrict__ Ch,
    int N, int K, int colb, int by)
{
    extern __shared__ char smg[];
    const uint32_t su = (uint32_t)__cvta_generic_to_shared(smg);

    const int tid  = threadIdx.x;
    const int lane = tid & 31;
    const int wid  = tid >> 5;
    const int wm = (wid & 1) * 64;
    const int wn = (wid >> 1) * 64;
    const int g  = lane >> 2;
    const int tg = lane & 3;
    const int lrow8 = (lane & 7) + ((lane >> 3) & 1) * 8;
    const int lhi   = lane >> 4;

    float acc[4][8][4];
    #pragma unroll
    for (int mt = 0; mt < 4; mt++)
        #pragma unroll
        for (int nt = 0; nt < 8; nt++)
            #pragma unroll
            for (int i = 0; i < 4; i++) acc[mt][nt][i] = 0.f;

    auto issue = [&](int stg) {
        const int st = stg % 3;
        const int k0 = stg * 32;
        const uint32_t ab = su + st * (A_ST + B_ST);
        const uint32_t bb = ab + A_ST;
        #pragma unroll
        for (int p = 0; p < 4; p++) {
            int idx = p * 128 + tid;
            int r = idx >> 2, c = idx & 3;
            cpa16(ab + r * A_STR + c * 16, A + (size_t)(by * 128 + r) * K + k0 + c * 8);
        }
        #pragma unroll
        for (int p = 0; p < 4; p++) {
            int idx = p * 128 + tid;
            int r = idx >> 4, c = idx & 15;
            cpa16(bb + r * B_STR + c * 16, B + (size_t)(k0 + r) * N + colb + c * 8);
        }
        cpa_commit();
    };

    const int nsteps = K / 32;
    issue(0); issue(1);

    for (int s = 0; s < nsteps; s++) {
        if (s + 1 < nsteps) cpa_wait<1>();
        else                cpa_wait<0>();
        __syncthreads();
        if (s + 2 < nsteps) issue(s + 2);

        const uint32_t ab = su + (s % 3) * (A_ST + B_ST);
        const uint32_t bb = ab + A_ST;

        #pragma unroll
        for (int kk = 0; kk < 32; kk += 16) {
            unsigned af[4][4], bf[4][4];
            #pragma unroll
            for (int mt = 0; mt < 4; mt++)
                ldsm4(af[mt], ab + (wm + mt * 16 + lrow8) * A_STR
                                 + ((kk >> 3) + lhi) * 16);
            #pragma unroll
            for (int ntp = 0; ntp < 4; ntp++)
                ldsm4t(bf[ntp], bb + (kk + lrow8) * B_STR
                                   + (((wn + ntp * 16) >> 3) + lhi) * 16);
            #pragma unroll
            for (int mt = 0; mt < 4; mt++)
                #pragma unroll
                for (int ntp = 0; ntp < 4; ntp++) {
                    mma16(acc[mt][2 * ntp],     af[mt], bf[ntp] + 0);
                    mma16(acc[mt][2 * ntp + 1], af[mt], bf[ntp] + 2);
                }
        }
    }

    #pragma unroll
    for (int mt = 0; mt < 4; mt++) {
        const int row = by * 128 + wm + mt * 16 + g;
        #pragma unroll
        for (int nt = 0; nt < 8; nt++) {
            const int col = colb + wn + nt * 8 + tg * 2;
            const float b0 = bias[col], b1 = bias[col + 1];
            float v0 = acc[mt][nt][0] + b0, v1 = acc[mt][nt][1] + b1;
            float v2 = acc[mt][nt][2] + b0, v3 = acc[mt][nt][3] + b1;
            if (Ch) {
                *(unsigned*)(Ch + (size_t)row * N + col)       = packh2(v0, v1);
                *(unsigned*)(Ch + (size_t)(row + 8) * N + col) = packh2(v2, v3);
            } else {
                *(float2*)(Cf + (size_t)row * N + col)       = make_float2(v0, v1);
                *(float2*)(Cf + (size_t)(row + 8) * N + col) = make_float2(v2, v3);
            }
        }
    }
}

// Fused QKV projection: bx 0..15 -> Wq, 16..19 -> Wk, 20..23 -> Wv
__global__ __launch_bounds__(128)
void gemm_qkv(const __half* __restrict__ x,
              const __half* __restrict__ Wq, const float* __restrict__ bq,
              const __half* __restrict__ Wk, const float* __restrict__ bk,
              const __half* __restrict__ Wv, const float* __restrict__ bv,
              __half* __restrict__ Qo, __half* __restrict__ Ko, __half* __restrict__ Vo)
{
    const int bx = blockIdx.x;
    const __half* B; const float* bias; __half* C; int N, colb;
    if (bx < 16)      { B = Wq; bias = bq; C = Qo; N = D_MODEL; colb = bx * 128; }
    else if (bx < 20) { B = Wk; bias = bk; C = Ko; N = KV_DIM;  colb = (bx - 16) * 128; }
    else              { B = Wv; bias = bv; C = Vo; N = KV_DIM;  colb = (bx - 20) * 128; }
    gemm_core(x, B, bias, nullptr, C, N, D_MODEL, colb, blockIdx.y);
}

__global__ __launch_bounds__(128)
void gemm_o(const __half* __restrict__ A, const __half* __restrict__ B,
            const float* __restrict__ bias, float* __restrict__ C)
{
    gemm_core(A, B, bias, C, nullptr, D_MODEL, D_MODEL, blockIdx.x * 128, blockIdx.y);
}

// ---------------------------------------------------------------------------
// Flash attention, fp16 MMA. 8 warps x 32 q-rows = 256/CTA.
// 3-stage KV ring, single barrier per tile; P via ex2.approx.f16x2.
// ---------------------------------------------------------------------------
#define KV_STR   144
#define KV_TILE  (64 * KV_STR)             // 9216 B (one of K or V)
#define KV_STAGE (2 * KV_TILE)             // K+V per stage
#define QROWS    256
#define Q_OFF    (3 * KV_STAGE)
#define ATTN_SMEM (Q_OFF + QROWS * KV_STR) // 92160 B
#define QSCALE (0.125f * 1.4426950408889634f)
#define NKT    (SEQ / 64)

__global__ __launch_bounds__(256)
void attn_f16(const __half* __restrict__ Q, const __half* __restrict__ K,
              const __half* __restrict__ V, __half* __restrict__ C)
{
    extern __shared__ char sma[];
    const uint32_t su = (uint32_t)__cvta_generic_to_shared(sma);
    const uint32_t qOff = su + Q_OFF;

    const int tid  = threadIdx.x;
    const int lane = tid & 31;
    const int wid  = tid >> 5;
    const int g    = lane >> 2;
    const int tg   = lane & 3;
    const int rA   = wid * 32;
    const int lrow8 = (lane & 7) + ((lane >> 3) & 1) * 8;
    const int lhi   = lane >> 4;

    const int qt = blockIdx.x;
    const int h  = blockIdx.y;
    const int b  = blockIdx.z;
    const int hkv = h >> 2;

    auto issueKV = [&](int kt) {
        const int st = kt % 3;
        #pragma unroll
        for (int p = 0; p < 4; p++) {
            int idx = p * 256 + tid;
            int sel = idx >> 9;
            int jj = (idx >> 3) & 63;
            int c  = idx & 7;
            const __half* src = (sel ? V : K)
                + (size_t)(b * SEQ + kt * 64 + jj) * KV_DIM + hkv * HDIM + c * 8;
            cpa16(su + st * KV_STAGE + sel * KV_TILE + jj * KV_STR + c * 16, src);
        }
        cpa_commit();
    };

    issueKV(0); issueKV(1);

    // Stage Q: fp16 -> fp32 scale -> fp16 -> smem
    #pragma unroll
    for (int p = 0; p < 32; p++) {
        int idx = p * 256 + tid;
        int r = idx >> 5, c2 = idx & 31;
        __half2 q2 = *(const __half2*)(Q + (size_t)(b * SEQ + qt * QROWS + r) * D_MODEL
                                         + h * HDIM + c2 * 2);
        float2 qf = __half22float2(q2);
        *(unsigned*)(sma + Q_OFF + r * KV_STR + c2 * 4) =
            packh2(qf.x * QSCALE, qf.y * QSCALE);
    }
    __syncthreads();

    unsigned aQ[2][4][4];
    #pragma unroll
    for (int bl = 0; bl < 2; bl++)
        #pragma unroll
        for (int kki = 0; kki < 4; kki++)
            ldsm4(aQ[bl][kki], qOff + (rA + bl * 16 + lrow8) * KV_STR
                                    + (kki * 2 + lhi) * 16);

    float o[2][8][4];
    #pragma unroll
    for (int bl = 0; bl < 2; bl++)
        #pragma unroll
        for (int nt = 0; nt < 8; nt++)
            #pragma unroll
            for (int i = 0; i < 4; i++) o[bl][nt][i] = 0.f;
    float m[2][2] = {{-1e30f, -1e30f}, {-1e30f, -1e30f}};
    float l[2][2] = {{0.f, 0.f}, {0.f, 0.f}};

    for (int kt = 0; kt < NKT; kt++) {
        if (kt + 1 < NKT) cpa_wait<1>();
        else              cpa_wait<0>();
        __syncthreads();
        if (kt + 2 < NKT) issueKV(kt + 2);

        const uint32_t kb = su + (kt % 3) * KV_STAGE;
        const uint32_t vb = kb + KV_TILE;

        // S = Q @ K^T (log2-scaled)
        float s[2][8][4];
        #pragma unroll
        for (int bl = 0; bl < 2; bl++)
            #pragma unroll
            for (int nt = 0; nt < 8; nt++)
                #pragma unroll
                for (int i = 0; i < 4; i++) s[bl][nt][i] = 0.f;

        #pragma unroll
        for (int kki = 0; kki < 4; kki++) {
            #pragma unroll
            for (int ntp = 0; ntp < 4; ntp++) {
                unsigned bK[4];
                ldsm4(bK, kb + (ntp * 16 + (lane & 7) + lhi * 8) * KV_STR
                             + (kki * 2 + ((lane >> 3) & 1)) * 16);
                mma16(s[0][2 * ntp],     aQ[0][kki], bK + 0);
                mma16(s[0][2 * ntp + 1], aQ[0][kki], bK + 2);
                mma16(s[1][2 * ntp],     aQ[1][kki], bK + 0);
                mma16(s[1][2 * ntp + 1], aQ[1][kki], bK + 2);
            }
        }

        // Online softmax (exp2 domain, f16x2 MUFU); P kept packed in ph
        unsigned ph[2][8][2];
        #pragma unroll
        for (int bl = 0; bl < 2; bl++) {
            float tm0 = -1e30f, tm1 = -1e30f;
            #pragma unroll
            for (int nt = 0; nt < 8; nt++) {
                tm0 = fmaxf(tm0, fmaxf(s[bl][nt][0], s[bl][nt][1]));
                tm1 = fmaxf(tm1, fmaxf(s[bl][nt][2], s[bl][nt][3]));
            }
            tm0 = fmaxf(tm0, __shfl_xor_sync(0xffffffffu, tm0, 1));
            tm0 = fmaxf(tm0, __shfl_xor_sync(0xffffffffu, tm0, 2));
            tm1 = fmaxf(tm1, __shfl_xor_sync(0xffffffffu, tm1, 1));
            tm1 = fmaxf(tm1, __shfl_xor_sync(0xffffffffu, tm1, 2));

            float nm0 = fmaxf(m[bl][0], tm0), nm1 = fmaxf(m[bl][1], tm1);
            float c0 = ex2(m[bl][0] - nm0), c1 = ex2(m[bl][1] - nm1);
            m[bl][0] = nm0; m[bl][1] = nm1;

            float rs0 = 0.f, rs1 = 0.f;
            #pragma unroll
            for (int nt = 0; nt < 8; nt++) {
                unsigned p01 = ex2h2(packh2(s[bl][nt][0] - nm0, s[bl][nt][1] - nm0));
                unsigned p23 = ex2h2(packh2(s[bl][nt][2] - nm1, s[bl][nt][3] - nm1));
                ph[bl][nt][0] = p01;
                ph[bl][nt][1] = p23;
                float2 f01 = unpackh2(p01);
                float2 f23 = unpackh2(p23);
                rs0 += f01.x + f01.y;
                rs1 += f23.x + f23.y;
                o[bl][nt][0] *= c0; o[bl][nt][1] *= c0;
                o[bl][nt][2] *= c1; o[bl][nt][3] *= c1;
            }
            rs0 += __shfl_xor_sync(0xffffffffu, rs0, 1);
            rs0 += __shfl_xor_sync(0xffffffffu, rs0, 2);
            rs1 += __shfl_xor_sync(0xffffffffu, rs1, 1);
            rs1 += __shfl_xor_sync(0xffffffffu, rs1, 2);
            l[bl][0] = l[bl][0] * c0 + rs0;
            l[bl][1] = l[bl][1] * c1 + rs1;
        }

        // O += P @ V (P already packed fp16)
        #pragma unroll
        for (int j = 0; j < 4; j++) {
            unsigned aP0[4], aP1[4];
            aP0[0] = ph[0][2 * j][0];     aP0[1] = ph[0][2 * j][1];
            aP0[2] = ph[0][2 * j + 1][0]; aP0[3] = ph[0][2 * j + 1][1];
            aP1[0] = ph[1][2 * j][0];     aP1[1] = ph[1][2 * j][1];
            aP1[2] = ph[1][2 * j + 1][0]; aP1[3] = ph[1][2 * j + 1][1];
            #pragma unroll
            for (int ntp = 0; ntp < 4; ntp++) {
                unsigned bV[4];
                ldsm4t(bV, vb + (j * 16 + lrow8) * KV_STR + (ntp * 2 + lhi) * 16);
                mma16(o[0][2 * ntp],     aP0, bV + 0);
                mma16(o[0][2 * ntp + 1], aP0, bV + 2);
                mma16(o[1][2 * ntp],     aP1, bV + 0);
                mma16(o[1][2 * ntp + 1], aP1, bV + 2);
            }
        }
    }

    // Normalize, write context fp16
    #pragma unroll
    for (int bl = 0; bl < 2; bl++) {
        const float i0 = 1.f / l[bl][0], i1 = 1.f / l[bl][1];
        #pragma unroll
        for (int nt = 0; nt < 8; nt++) {
            const size_t row = (size_t)(b * SEQ + qt * QROWS + rA + bl * 16 + g);
            const int col = h * HDIM + nt * 8 + tg * 2;
            *(unsigned*)(C + row * D_MODEL + col) =
                packh2(o[bl][nt][0] * i0, o[bl][nt][1] * i0);
            *(unsigned*)(C + (row + 8) * D_MODEL + col) =
                packh2(o[bl][nt][2] * i1, o[bl][nt][3] * i1);
        }
    }
}

// ---------------------------------------------------------------------------
// Launch
// ---------------------------------------------------------------------------
extern "C" void kernel_launch(void* const* d_in, const int* in_sizes, int n_in,
                              void* d_out, int out_size)
{
    const float* x  = (const float*)d_in[0];
    const float* Wq = (const float*)d_in[1];
    const float* bq = (const float*)d_in[2];
    const float* Wk = (const float*)d_in[3];
    const float* bk = (const float*)d_in[4];
    const float* Wv = (const float*)d_in[5];
    const float* bv = (const float*)d_in[6];
    const float* Wo = (const float*)d_in[7];
    const float* bo = (const float*)d_in[8];
    float* out = (float*)d_out;

    __half *pX, *pWq, *pWk, *pWv, *pWo, *pQ, *pK, *pV, *pC;
    cudaGetSymbolAddress((void**)&pX, g_X);
    cudaGetSymbolAddress((void**)&pWq, g_Wq);
    cudaGetSymbolAddress((void**)&pWk, g_Wk);
    cudaGetSymbolAddress((void**)&pWv, g_Wv);
    cudaGetSymbolAddress((void**)&pWo, g_Wo);
    cudaGetSymbolAddress((void**)&pQ, g_Q);
    cudaGetSymbolAddress((void**)&pK, g_K);
    cudaGetSymbolAddress((void**)&pV, g_V);
    cudaGetSymbolAddress((void**)&pC, g_C);

    cudaFuncSetAttribute(gemm_qkv, cudaFuncAttributeMaxDynamicSharedMemorySize, GEMM_SMEM);
    cudaFuncSetAttribute(gemm_o,   cudaFuncAttributeMaxDynamicSharedMemorySize, GEMM_SMEM);
    cudaFuncSetAttribute(attn_f16, cudaFuncAttributeMaxDynamicSharedMemorySize, ATTN_SMEM);

    // Fused pre-pass: fp32 -> fp16 for all inputs
    cvt_all<<<SEG4 / 256, 256>>>((const float4*)x,  (const float4*)Wq,
                                 (const float4*)Wk, (const float4*)Wv,
                                 (const float4*)Wo,
                                 (uint2*)pX, (uint2*)pWq, (uint2*)pWk,
                                 (uint2*)pWv, (uint2*)pWo);

    // Fused QKV projection (fp16 outputs)
    gemm_qkv<<<dim3(24, MTOK / 128), 128, GEMM_SMEM>>>(
        pX, pWq, bq, pWk, bk, pWv, bv, pQ, pK, pV);

    // Attention
    attn_f16<<<dim3(SEQ / QROWS, HEADS, BATCH), 256, ATTN_SMEM>>>(pQ, pK, pV, pC);

    // Output projection (fp32 output)
    gemm_o<<<dim3(D_MODEL / 128, MTOK / 128), 128, GEMM_SMEM>>>(pC, pWo, bo, out);
}